// round 5
// baseline (speedup 1.0000x reference)
#include <cuda_runtime.h>
#include <cuda_bf16.h>
#include <cstdint>

#define B_SZ 8192
#define D_SZ 512
#define U_SZ 512
#define M_SZ 16

// ---------------------------------------------------------------------------
// Scratch (static __device__ — no allocations allowed)
// ---------------------------------------------------------------------------
__device__ float g_sim[B_SZ * M_SZ];            // sim/16
__device__ float g_sx[B_SZ];                    // x row scales
__device__ float g_sw[M_SZ * U_SZ];             // W column scales
__device__ float g_swi[M_SZ * U_SZ];            // 1/scale
__device__ char  g_x1[B_SZ * D_SZ];             // x hi limb
__device__ char  g_x0[B_SZ * D_SZ];             // x lo limb
__device__ char  g_w1[M_SZ * U_SZ * D_SZ];      // [m][u][d] hi limb (k-major)
__device__ char  g_w0[M_SZ * U_SZ * D_SZ];      // lo limb

// ---------------------------------------------------------------------------
// helpers
// ---------------------------------------------------------------------------
__device__ __forceinline__ uint32_t smem_u32(const void* p) {
    uint32_t a;
    asm("{ .reg .u64 t; cvta.to.shared.u64 t, %1; cvt.u32.u64 %0, t; }"
        : "=r"(a) : "l"(p));
    return a;
}
__device__ __forceinline__ void cp_async16(uint32_t saddr, const void* gaddr) {
    asm volatile("cp.async.cg.shared.global [%0], [%1], 16;"
                 :: "r"(saddr), "l"(gaddr) : "memory");
}
__device__ __forceinline__ void mma_s8(int* c, const uint32_t* a, const uint32_t* b) {
    asm volatile(
        "mma.sync.aligned.m16n8k32.row.col.s32.s8.s8.s32 "
        "{%0,%1,%2,%3}, {%4,%5,%6,%7}, {%8,%9}, {%0,%1,%2,%3};"
        : "+r"(c[0]), "+r"(c[1]), "+r"(c[2]), "+r"(c[3])
        : "r"(a[0]), "r"(a[1]), "r"(a[2]), "r"(a[3]), "r"(b[0]), "r"(b[1]));
}
__device__ __forceinline__ uint32_t lds32(const char* p) {
    return *reinterpret_cast<const uint32_t*>(p);
}
// two-limb int8 quantization
__device__ __forceinline__ void q2(float f, float s, float si, int& i1, int& i0) {
    i1 = __float2int_rn(f * si);
    float r = f - (float)i1 * s;
    i0 = __float2int_rn(r * si * 128.f);
}
__device__ __forceinline__ int pk4(int b0, int b1, int b2, int b3) {
    return (b0 & 0xff) | ((b1 & 0xff) << 8) | ((b2 & 0xff) << 16) | ((b3 & 0xff) << 24);
}

// ---------------------------------------------------------------------------
// Prep: per-row two-limb int8 quantization of x. One warp per row.
// ---------------------------------------------------------------------------
__global__ __launch_bounds__(256) void quant_x(const float* __restrict__ x) {
    int row = blockIdx.x * 8 + (threadIdx.x >> 5);
    int lane = threadIdx.x & 31;
    const float4* xr = reinterpret_cast<const float4*>(x + (size_t)row * D_SZ);
    float4 v[4];
    float mx = 0.f;
#pragma unroll
    for (int j = 0; j < 4; j++) {
        v[j] = xr[lane * 4 + j];
        mx = fmaxf(mx, fmaxf(fmaxf(fabsf(v[j].x), fabsf(v[j].y)),
                             fmaxf(fabsf(v[j].z), fabsf(v[j].w))));
    }
#pragma unroll
    for (int o = 16; o; o >>= 1) mx = fmaxf(mx, __shfl_xor_sync(~0u, mx, o));
    mx = fmaxf(mx, 1e-20f);
    float s = mx / 127.f, si = 127.f / mx;
    if (lane == 0) g_sx[row] = s;
    int p1[4], p0[4];
#pragma unroll
    for (int j = 0; j < 4; j++) {
        int a1, a0, b1, b0, c1, c0, d1, d0;
        q2(v[j].x, s, si, a1, a0); q2(v[j].y, s, si, b1, b0);
        q2(v[j].z, s, si, c1, c0); q2(v[j].w, s, si, d1, d0);
        p1[j] = pk4(a1, b1, c1, d1);
        p0[j] = pk4(a0, b0, c0, d0);
    }
    *reinterpret_cast<int4*>(g_x1 + (size_t)row * D_SZ + lane * 16) =
        make_int4(p1[0], p1[1], p1[2], p1[3]);
    *reinterpret_cast<int4*>(g_x0 + (size_t)row * D_SZ + lane * 16) =
        make_int4(p0[0], p0[1], p0[2], p0[3]);
}

// ---------------------------------------------------------------------------
// Prep: per-(m,u)-column abs-max of kernels[m][d][u]
// ---------------------------------------------------------------------------
__global__ __launch_bounds__(256) void quant_w_scale(const float* __restrict__ k) {
    __shared__ float red[8][32];
    int m = blockIdx.x, u0 = blockIdx.y * 32;
    int ud = threadIdx.x & 31, dg = threadIdx.x >> 5;
    float mx = 0.f;
    const float* base = k + ((size_t)m * D_SZ + dg * 64) * U_SZ + u0 + ud;
    for (int dd = 0; dd < 64; dd++)
        mx = fmaxf(mx, fabsf(base[(size_t)dd * U_SZ]));
    red[dg][ud] = mx;
    __syncthreads();
    if (threadIdx.x < 32) {
        float m2 = red[0][threadIdx.x];
#pragma unroll
        for (int g = 1; g < 8; g++) m2 = fmaxf(m2, red[g][threadIdx.x]);
        m2 = fmaxf(m2, 1e-20f);
        g_sw[m * U_SZ + u0 + threadIdx.x] = m2 / 127.f;
        g_swi[m * U_SZ + u0 + threadIdx.x] = 127.f / m2;
    }
}

// ---------------------------------------------------------------------------
// Prep: kernels [m][d][u] fp32 -> transposed two-limb int8 [m][u][d]
// ---------------------------------------------------------------------------
__global__ __launch_bounds__(256) void quant_w(const float* __restrict__ k) {
    __shared__ float t[32][33];
    int m = blockIdx.z, d0 = blockIdx.x * 32, u0 = blockIdx.y * 32;
    int tx = threadIdx.x, ty = threadIdx.y;
    const float* src = k + (size_t)m * D_SZ * U_SZ;
#pragma unroll
    for (int j = 0; j < 4; j++)
        t[ty + 8 * j][tx] = src[(size_t)(d0 + ty + 8 * j) * U_SZ + u0 + tx];
    __syncthreads();
#pragma unroll
    for (int j = 0; j < 4; j++) {
        int u = u0 + ty + 8 * j;
        float s = g_sw[m * U_SZ + u], si = g_swi[m * U_SZ + u];
        float v = t[tx][ty + 8 * j];
        int i1, i0;
        q2(v, s, si, i1, i0);
        size_t oi = ((size_t)m * U_SZ + u) * D_SZ + d0 + tx;
        g_w1[oi] = (char)i1;
        g_w0[oi] = (char)i0;
    }
}

// ---------------------------------------------------------------------------
// sim kernel (verified R1) — stores sim/16
// ---------------------------------------------------------------------------
__global__ __launch_bounds__(128) void sim_kernel(
    const float* __restrict__ x, const float* __restrict__ key_kernel,
    const float* __restrict__ key_bias, const float* __restrict__ keys_map)
{
    __shared__ float xs[16 * D_SZ];
    __shared__ float kv[16][64];
    int tid = threadIdx.x;
    int b0 = blockIdx.x * 16;
    for (int i = tid; i < 16 * D_SZ; i += 128) xs[i] = x[b0 * D_SZ + i];
    __syncthreads();
    int k = tid & 63, rg = tid >> 6;
    float acc[8];
#pragma unroll
    for (int r = 0; r < 8; r++) acc[r] = 0.f;
    for (int d = 0; d < D_SZ; d++) {
        float kkv = key_kernel[d * 64 + k];
#pragma unroll
        for (int r = 0; r < 8; r++) acc[r] += xs[(rg + 2 * r) * D_SZ + d] * kkv;
    }
    float kb = key_bias[k];
#pragma unroll
    for (int r = 0; r < 8; r++) kv[rg + 2 * r][k] = acc[r] + kb;
    __syncthreads();
    int r = tid >> 3, m0 = tid & 7;
#pragma unroll
    for (int h = 0; h < 2; h++) {
        int m = m0 + h * 8;
        float d2 = 0.f;
#pragma unroll 8
        for (int kk = 0; kk < 64; kk++) {
            float diff = kv[r][kk] - keys_map[m * 64 + kk];
            d2 += diff * diff;
        }
        g_sim[(b0 + r) * M_SZ + m] = 1.0f / (16.0f * (sqrtf(d2) + 1.0f));
    }
}

// ---------------------------------------------------------------------------
// Main int8 MMA GEMM. 128x128 tile, k-chunk 32, limb terms:
//   macc1 += X1*W1 ; macc2 += X1*W0 + X0*W1   (int32, exact)
// fold per mode: facc += (sim/16*sx)*sw*(macc1 + macc2/128)
// Row stride 48B: conflict-free LDS + 16B-aligned cp.async.
// ---------------------------------------------------------------------------
#define RS 48
#define TIL (128 * RS)              // 6144
#define STG (4 * TIL)               // 24576: X1 | X0 | W1 | W0
#define SM_BIAS (3 * STG)           // 73728
#define SM_SIM  (SM_BIAS + 16 * 128 * 4)
#define SM_SX   (SM_SIM + 128 * 16 * 4)
#define SM_SW   (SM_SX + 128 * 4)
#define SMEM_TOTAL (SM_SW + 16 * 128 * 4)     // 98816

__device__ __forceinline__ void issue_loads(
    uint32_t st, int brow0, int bcol0, int m, int d0, int tid)
{
#pragma unroll
    for (int j = 0; j < 2; j++) {
        int idx = tid + j * 512;            // 1024 chunks of 16B
        int tile = idx >> 8;
        int row = (idx >> 1) & 127;
        int seg = idx & 1;
        uint32_t dst = st + tile * TIL + row * RS + seg * 16;
        const char* g;
        if (tile == 0)
            g = g_x1 + (size_t)(brow0 + row) * D_SZ + d0 + seg * 16;
        else if (tile == 1)
            g = g_x0 + (size_t)(brow0 + row) * D_SZ + d0 + seg * 16;
        else if (tile == 2)
            g = g_w1 + ((size_t)m * U_SZ + bcol0 + row) * D_SZ + d0 + seg * 16;
        else
            g = g_w0 + ((size_t)m * U_SZ + bcol0 + row) * D_SZ + d0 + seg * 16;
        cp_async16(dst, g);
    }
}

__global__ __launch_bounds__(512, 1) void pd_mma(
    const float* __restrict__ biases, float* __restrict__ out)
{
    extern __shared__ __align__(1024) char smem[];
    uint32_t sb = smem_u32(smem);
    int tid = threadIdx.x;
    int lane = tid & 31, warp = tid >> 5;
    int wm = warp & 3, wn = warp >> 2;     // 4 x 4 warp grid, warp tile 32x32
    int brow0 = blockIdx.y * 128;
    int bcol0 = blockIdx.x * 128;

    float* bias_sm = reinterpret_cast<float*>(smem + SM_BIAS);   // [16][128]
    float* sim_sm  = reinterpret_cast<float*>(smem + SM_SIM);    // [128][16]
    float* sx_sm   = reinterpret_cast<float*>(smem + SM_SX);     // [128]
    float* sw_sm   = reinterpret_cast<float*>(smem + SM_SW);     // [16][128]
    for (int i = tid; i < 16 * 128; i += 512) {
        bias_sm[i] = biases[(i >> 7) * U_SZ + bcol0 + (i & 127)];
        sw_sm[i]   = g_sw[(i >> 7) * U_SZ + bcol0 + (i & 127)];
    }
    for (int i = tid; i < 128 * 16; i += 512)
        sim_sm[i] = g_sim[(brow0 + (i >> 4)) * M_SZ + (i & 15)];
    if (tid < 128) sx_sm[tid] = g_sx[brow0 + tid];

    // fragment LDS offsets (within a tile; lane layout of m16n8k32 .s8)
    int lq = lane >> 2, lr = lane & 3;
    uint32_t abase[2], bbase[4];
#pragma unroll
    for (int mt = 0; mt < 2; mt++)
        abase[mt] = (uint32_t)((wm * 32 + mt * 16 + lq) * RS + lr * 4);
#pragma unroll
    for (int nt = 0; nt < 4; nt++)
        bbase[nt] = (uint32_t)((wn * 32 + nt * 8 + lq) * RS + lr * 4);

    int   macc1[2][4][4], macc2[2][4][4];
    float facc[2][4][4];
#pragma unroll
    for (int mt = 0; mt < 2; mt++)
#pragma unroll
        for (int nt = 0; nt < 4; nt++)
#pragma unroll
            for (int i = 0; i < 4; i++) {
                macc1[mt][nt][i] = 0; macc2[mt][nt][i] = 0; facc[mt][nt][i] = 0.f;
            }

    // prologue: stages 0,1
    issue_loads(sb, brow0, bcol0, 0, 0, tid);
    asm volatile("cp.async.commit_group;" ::: "memory");
    issue_loads(sb + STG, brow0, bcol0, 0, 32, tid);
    asm volatile("cp.async.commit_group;" ::: "memory");

    for (int it = 0; it < 256; it++) {
        asm volatile("cp.async.wait_group 1;" ::: "memory");
        __syncthreads();
        int it2 = it + 2;
        if (it2 < 256)
            issue_loads(sb + (it2 % 3) * STG, brow0, bcol0,
                        it2 >> 4, (it2 & 15) * 32, tid);
        asm volatile("cp.async.commit_group;" ::: "memory");

        const char* st = smem + (it % 3) * STG;

        uint32_t b1f[4][2], b0f[4][2];
#pragma unroll
        for (int nt = 0; nt < 4; nt++) {
            b1f[nt][0] = lds32(st + 2 * TIL + bbase[nt]);
            b1f[nt][1] = lds32(st + 2 * TIL + bbase[nt] + 16);
            b0f[nt][0] = lds32(st + 3 * TIL + bbase[nt]);
            b0f[nt][1] = lds32(st + 3 * TIL + bbase[nt] + 16);
        }
#pragma unroll
        for (int mt = 0; mt < 2; mt++) {
            uint32_t a1f[4], a0f[4];
            a1f[0] = lds32(st + abase[mt]);
            a1f[1] = lds32(st + abase[mt] + 8 * RS);
            a1f[2] = lds32(st + abase[mt] + 16);
            a1f[3] = lds32(st + abase[mt] + 8 * RS + 16);
            a0f[0] = lds32(st + TIL + abase[mt]);
            a0f[1] = lds32(st + TIL + abase[mt] + 8 * RS);
            a0f[2] = lds32(st + TIL + abase[mt] + 16);
            a0f[3] = lds32(st + TIL + abase[mt] + 8 * RS + 16);
#pragma unroll
            for (int nt = 0; nt < 4; nt++) {
                mma_s8(macc1[mt][nt], a1f, b1f[nt]);   // X1*W1
                mma_s8(macc2[mt][nt], a1f, b0f[nt]);   // X1*W0
                mma_s8(macc2[mt][nt], a0f, b1f[nt]);   // X0*W1
            }
        }

        if ((it & 15) == 15) {        // mode boundary: fold int partials
            int m = it >> 4;
#pragma unroll
            for (int mt = 0; mt < 2; mt++) {
                int ra = wm * 32 + mt * 16 + lq;
                float cA = sim_sm[ra * 16 + m] * sx_sm[ra];
                float cB = sim_sm[(ra + 8) * 16 + m] * sx_sm[ra + 8];
#pragma unroll
                for (int nt = 0; nt < 4; nt++) {
                    int c0 = wn * 32 + nt * 8 + 2 * lr;
                    float w0 = sw_sm[m * 128 + c0];
                    float w1 = sw_sm[m * 128 + c0 + 1];
                    float v0 = (float)macc1[mt][nt][0] +
                               0.0078125f * (float)macc2[mt][nt][0];
                    float v1 = (float)macc1[mt][nt][1] +
                               0.0078125f * (float)macc2[mt][nt][1];
                    float v2 = (float)macc1[mt][nt][2] +
                               0.0078125f * (float)macc2[mt][nt][2];
                    float v3 = (float)macc1[mt][nt][3] +
                               0.0078125f * (float)macc2[mt][nt][3];
                    facc[mt][nt][0] += cA * w0 * v0;
                    facc[mt][nt][1] += cA * w1 * v1;
                    facc[mt][nt][2] += cB * w0 * v2;
                    facc[mt][nt][3] += cB * w1 * v3;
                    macc1[mt][nt][0] = 0; macc1[mt][nt][1] = 0;
                    macc1[mt][nt][2] = 0; macc1[mt][nt][3] = 0;
                    macc2[mt][nt][0] = 0; macc2[mt][nt][1] = 0;
                    macc2[mt][nt][2] = 0; macc2[mt][nt][3] = 0;
                }
            }
        }
    }

    // bias fold:  facc += sum_m (sim/16)[row,m] * biases[m,col]
#pragma unroll
    for (int mt = 0; mt < 2; mt++) {
        int ra = wm * 32 + mt * 16 + lq;
        for (int m = 0; m < 16; m++) {
            float sa = sim_sm[ra * 16 + m];
            float sb_ = sim_sm[(ra + 8) * 16 + m];
#pragma unroll
            for (int nt = 0; nt < 4; nt++) {
                int col = wn * 32 + nt * 8 + 2 * lr;
                float b0 = bias_sm[m * 128 + col];
                float b1 = bias_sm[m * 128 + col + 1];
                facc[mt][nt][0] += sa * b0;  facc[mt][nt][1] += sa * b1;
                facc[mt][nt][2] += sb_ * b0; facc[mt][nt][3] += sb_ * b1;
            }
        }
    }

    // store
#pragma unroll
    for (int mt = 0; mt < 2; mt++) {
        int ra = brow0 + wm * 32 + mt * 16 + lq;
#pragma unroll
        for (int nt = 0; nt < 4; nt++) {
            int col = bcol0 + wn * 32 + nt * 8 + 2 * lr;
            *reinterpret_cast<float2*>(&out[(size_t)ra * U_SZ + col]) =
                make_float2(facc[mt][nt][0], facc[mt][nt][1]);
            *reinterpret_cast<float2*>(&out[(size_t)(ra + 8) * U_SZ + col]) =
                make_float2(facc[mt][nt][2], facc[mt][nt][3]);
        }
    }
}

// ---------------------------------------------------------------------------
extern "C" void kernel_launch(void* const* d_in, const int* in_sizes, int n_in,
                              void* d_out, int out_size)
{
    const float* x          = (const float*)d_in[0];
    const float* key_kernel = (const float*)d_in[1];
    const float* key_bias   = (const float*)d_in[2];
    const float* keys_map   = (const float*)d_in[3];
    const float* kernels    = (const float*)d_in[4];
    const float* biases     = (const float*)d_in[5];
    float* out = (float*)d_out;

    cudaFuncSetAttribute(pd_mma, cudaFuncAttributeMaxDynamicSharedMemorySize,
                         SMEM_TOTAL);

    quant_x<<<B_SZ / 8, 256>>>(x);
    quant_w_scale<<<dim3(16, 16), 256>>>(kernels);
    quant_w<<<dim3(16, 16, 16), dim3(32, 8)>>>(kernels);
    sim_kernel<<<B_SZ / 16, 128>>>(x, key_kernel, key_bias, keys_map);

    dim3 grid(U_SZ / 128, B_SZ / 128);
    pd_mma<<<grid, 512, SMEM_TOTAL>>>(biases, out);
}

// round 6
// speedup vs baseline: 3.2884x; 3.2884x over previous
#include <cuda_runtime.h>
#include <cuda_fp16.h>
#include <cstdint>

#define B_SZ 8192
#define D_SZ 512
#define U_SZ 512
#define M_SZ 16

// ---------------------------------------------------------------------------
// Scratch (static __device__ — no allocations allowed)
// ---------------------------------------------------------------------------
__device__ float  g_sim[B_SZ * M_SZ];          // sim/16
__device__ __half g_xhi[B_SZ * D_SZ];
__device__ __half g_xlo[B_SZ * D_SZ];
__device__ __half g_wh[M_SZ * U_SZ * D_SZ];    // [m][u][d]  (k-major B)

// ---------------------------------------------------------------------------
// helpers
// ---------------------------------------------------------------------------
__device__ __forceinline__ uint32_t smem_u32(const void* p) {
    uint32_t a;
    asm("{ .reg .u64 t; cvta.to.shared.u64 t, %1; cvt.u32.u64 %0, t; }"
        : "=r"(a) : "l"(p));
    return a;
}
__device__ __forceinline__ void cp_async16(uint32_t saddr, const void* gaddr) {
    asm volatile("cp.async.cg.shared.global [%0], [%1], 16;"
                 :: "r"(saddr), "l"(gaddr) : "memory");
}
__device__ __forceinline__ void ldsm4(uint32_t* r, uint32_t a) {
    asm volatile("ldmatrix.sync.aligned.m8n8.x4.shared.b16 {%0,%1,%2,%3}, [%4];"
                 : "=r"(r[0]), "=r"(r[1]), "=r"(r[2]), "=r"(r[3]) : "r"(a));
}
__device__ __forceinline__ void mma16816(float* c, const uint32_t* a, const uint32_t* b) {
    asm volatile(
        "mma.sync.aligned.m16n8k16.row.col.f32.f16.f16.f32 "
        "{%0,%1,%2,%3}, {%4,%5,%6,%7}, {%8,%9}, {%0,%1,%2,%3};"
        : "+f"(c[0]), "+f"(c[1]), "+f"(c[2]), "+f"(c[3])
        : "r"(a[0]), "r"(a[1]), "r"(a[2]), "r"(a[3]), "r"(b[0]), "r"(b[1]));
}

// ---------------------------------------------------------------------------
// Prep: fp32 -> fp16 hi + fp16 residual of x
// ---------------------------------------------------------------------------
__global__ __launch_bounds__(256) void conv_x(const float* __restrict__ x) {
    size_t i = ((size_t)blockIdx.x * 256 + threadIdx.x) * 4;
    float4 v = *reinterpret_cast<const float4*>(x + i);
    __half h0 = __float2half_rn(v.x), h1 = __float2half_rn(v.y);
    __half h2 = __float2half_rn(v.z), h3 = __float2half_rn(v.w);
    __half l0 = __float2half_rn(v.x - __half2float(h0));
    __half l1 = __float2half_rn(v.y - __half2float(h1));
    __half l2 = __float2half_rn(v.z - __half2float(h2));
    __half l3 = __float2half_rn(v.w - __half2float(h3));
    __half2* ph = reinterpret_cast<__half2*>(g_xhi + i);
    __half2* pl = reinterpret_cast<__half2*>(g_xlo + i);
    ph[0] = __halves2half2(h0, h1); ph[1] = __halves2half2(h2, h3);
    pl[0] = __halves2half2(l0, l1); pl[1] = __halves2half2(l2, l3);
}

// ---------------------------------------------------------------------------
// Prep: kernels [m][d][u] fp32 -> transposed fp16 [m][u][d]
// ---------------------------------------------------------------------------
__global__ __launch_bounds__(256) void conv_w(const float* __restrict__ k) {
    __shared__ float t[32][33];
    int m = blockIdx.z, d0 = blockIdx.x * 32, u0 = blockIdx.y * 32;
    int tx = threadIdx.x, ty = threadIdx.y;
    const float* src = k + (size_t)m * D_SZ * U_SZ;
#pragma unroll
    for (int j = 0; j < 4; j++)
        t[ty + 8 * j][tx] = src[(size_t)(d0 + ty + 8 * j) * U_SZ + u0 + tx];
    __syncthreads();
    size_t ob = (size_t)m * U_SZ * D_SZ;
#pragma unroll
    for (int j = 0; j < 4; j++) {
        float v = t[tx][ty + 8 * j];
        g_wh[ob + (size_t)(u0 + ty + 8 * j) * D_SZ + d0 + tx] = __float2half_rn(v);
    }
}

// ---------------------------------------------------------------------------
// sim kernel (verified R1) — stores sim/16
// ---------------------------------------------------------------------------
__global__ __launch_bounds__(128) void sim_kernel(
    const float* __restrict__ x, const float* __restrict__ key_kernel,
    const float* __restrict__ key_bias, const float* __restrict__ keys_map)
{
    __shared__ float xs[16 * D_SZ];
    __shared__ float kv[16][64];
    int tid = threadIdx.x;
    int b0 = blockIdx.x * 16;
    for (int i = tid; i < 16 * D_SZ; i += 128) xs[i] = x[b0 * D_SZ + i];
    __syncthreads();
    int k = tid & 63, rg = tid >> 6;
    float acc[8];
#pragma unroll
    for (int r = 0; r < 8; r++) acc[r] = 0.f;
    for (int d = 0; d < D_SZ; d++) {
        float kkv = key_kernel[d * 64 + k];
#pragma unroll
        for (int r = 0; r < 8; r++) acc[r] += xs[(rg + 2 * r) * D_SZ + d] * kkv;
    }
    float kb = key_bias[k];
#pragma unroll
    for (int r = 0; r < 8; r++) kv[rg + 2 * r][k] = acc[r] + kb;
    __syncthreads();
    int r = tid >> 3, m0 = tid & 7;
#pragma unroll
    for (int h = 0; h < 2; h++) {
        int m = m0 + h * 8;
        float d2 = 0.f;
#pragma unroll 8
        for (int kk = 0; kk < 64; kk++) {
            float diff = kv[r][kk] - keys_map[m * 64 + kk];
            d2 += diff * diff;
        }
        g_sim[(b0 + r) * M_SZ + m] = 1.0f / (16.0f * (sqrtf(d2) + 1.0f));
    }
}

// ---------------------------------------------------------------------------
// Main HMMA GEMM. 128x128 tile, BK=32, fp16 2-term (AhiB + AloB), 3-stage
// cp.async, 16 warps (4x4 grid, warp tile 32x32), ONE barrier per iteration,
// mode fold every 16 chunks (sim applied to fp32 partials in registers).
// ---------------------------------------------------------------------------
#define ROWB 80          // padded smem row stride (bytes) for 32 fp16 cols
#define TILEB (128 * ROWB)          // 10240
#define STAGEB (3 * TILEB)          // Ahi | Alo | B = 30720
#define SM_BIAS (3 * STAGEB)        // 92160
#define SM_SIM  (SM_BIAS + 16 * 128 * 4)
#define SMEM_TOTAL (SM_SIM + 128 * 16 * 4)   // 108544

__device__ __forceinline__ void issue_loads(
    uint32_t st, int brow0, int bcol0, int m, int d0, int tid)
{
    int row = tid >> 2, seg = tid & 3;           // 512 threads: 1 cp16 per tile
    uint32_t so = (uint32_t)(row * ROWB + seg * 16);
    cp_async16(st + so,
               g_xhi + (size_t)(brow0 + row) * D_SZ + d0 + seg * 8);
    cp_async16(st + TILEB + so,
               g_xlo + (size_t)(brow0 + row) * D_SZ + d0 + seg * 8);
    cp_async16(st + 2 * TILEB + so,
               g_wh + ((size_t)m * U_SZ + bcol0 + row) * D_SZ + d0 + seg * 8);
}

__global__ __launch_bounds__(512, 1) void pd_mma(
    const float* __restrict__ biases, float* __restrict__ out)
{
    extern __shared__ __align__(1024) char smem[];
    uint32_t sb = smem_u32(smem);
    int tid = threadIdx.x;
    int lane = tid & 31, warp = tid >> 5;
    int wm = warp & 3, wn = warp >> 2;     // 4 x 4 warp grid
    int brow0 = blockIdx.y * 128;
    int bcol0 = blockIdx.x * 128;

    float* bias_sm = reinterpret_cast<float*>(smem + SM_BIAS);   // [16][128]
    float* sim_sm  = reinterpret_cast<float*>(smem + SM_SIM);    // [128][16]
    for (int i = tid; i < 16 * 128; i += 512)
        bias_sm[i] = biases[(i >> 7) * U_SZ + bcol0 + (i & 127)];
    for (int i = tid; i < 128 * 16; i += 512)
        sim_sm[i] = g_sim[(brow0 + (i >> 4)) * M_SZ + (i & 15)];

    // ldmatrix smem offsets (relative to stage/tile base)
    uint32_t aoff[2], boff[2];
#pragma unroll
    for (int mt = 0; mt < 2; mt++)
        aoff[mt] = (uint32_t)((wm * 32 + mt * 16 + (lane & 15)) * ROWB +
                              ((lane >> 4) * 16));
#pragma unroll
    for (int p = 0; p < 2; p++)
        boff[p] = (uint32_t)((wn * 32 + p * 16 + ((lane >> 4) * 8) + (lane & 7)) * ROWB +
                             (((lane >> 3) & 1) * 16));

    float macc[2][4][4], facc[2][4][4];
#pragma unroll
    for (int mt = 0; mt < 2; mt++)
#pragma unroll
        for (int nt = 0; nt < 4; nt++)
#pragma unroll
            for (int i = 0; i < 4; i++) { macc[mt][nt][i] = 0.f; facc[mt][nt][i] = 0.f; }

    // prologue: stages 0,1
    issue_loads(sb, brow0, bcol0, 0, 0, tid);
    asm volatile("cp.async.commit_group;" ::: "memory");
    issue_loads(sb + STAGEB, brow0, bcol0, 0, 32, tid);
    asm volatile("cp.async.commit_group;" ::: "memory");

    for (int it = 0; it < 256; it++) {
        // group `it` complete (in-order completion; committed so far: 0..it+1)
        asm volatile("cp.async.wait_group 1;" ::: "memory");
        // visibility of group `it` across threads + all warps finished
        // reading stage (it-1)%3 (ldsm are synchronous register loads)
        __syncthreads();
        int it2 = it + 2;
        if (it2 < 256)
            issue_loads(sb + (it2 % 3) * STAGEB, brow0, bcol0,
                        it2 >> 4, (it2 & 15) * 32, tid);
        asm volatile("cp.async.commit_group;" ::: "memory");

        uint32_t st = sb + (it % 3) * STAGEB;
#pragma unroll
        for (int ks = 0; ks < 2; ks++) {
            uint32_t ah[2][4], al[2][4], bh[2][4];
#pragma unroll
            for (int mt = 0; mt < 2; mt++) {
                ldsm4(ah[mt], st + aoff[mt] + ks * 32);
                ldsm4(al[mt], st + TILEB + aoff[mt] + ks * 32);
            }
#pragma unroll
            for (int p = 0; p < 2; p++)
                ldsm4(bh[p], st + 2 * TILEB + boff[p] + ks * 32);
            // term 1: Ahi * B
#pragma unroll
            for (int mt = 0; mt < 2; mt++)
#pragma unroll
                for (int p = 0; p < 2; p++) {
                    mma16816(macc[mt][2 * p],     ah[mt], &bh[p][0]);
                    mma16816(macc[mt][2 * p + 1], ah[mt], &bh[p][2]);
                }
            // term 2: Alo * B
#pragma unroll
            for (int mt = 0; mt < 2; mt++)
#pragma unroll
                for (int p = 0; p < 2; p++) {
                    mma16816(macc[mt][2 * p],     al[mt], &bh[p][0]);
                    mma16816(macc[mt][2 * p + 1], al[mt], &bh[p][2]);
                }
        }

        if ((it & 15) == 15) {        // mode boundary: fold partials
            int m = it >> 4;
#pragma unroll
            for (int mt = 0; mt < 2; mt++) {
                int ra = wm * 32 + mt * 16 + (lane >> 2);
                float sa = sim_sm[ra * 16 + m];
                float sb_ = sim_sm[(ra + 8) * 16 + m];
#pragma unroll
                for (int nt = 0; nt < 4; nt++) {
                    facc[mt][nt][0] += sa  * macc[mt][nt][0];
                    facc[mt][nt][1] += sa  * macc[mt][nt][1];
                    facc[mt][nt][2] += sb_ * macc[mt][nt][2];
                    facc[mt][nt][3] += sb_ * macc[mt][nt][3];
                    macc[mt][nt][0] = 0.f; macc[mt][nt][1] = 0.f;
                    macc[mt][nt][2] = 0.f; macc[mt][nt][3] = 0.f;
                }
            }
        }
    }

    // bias fold:  facc += sum_m (sim/16)[row,m] * biases[m,col]
#pragma unroll
    for (int mt = 0; mt < 2; mt++) {
        int ra = wm * 32 + mt * 16 + (lane >> 2);
        for (int m = 0; m < 16; m++) {
            float sa = sim_sm[ra * 16 + m];
            float sb_ = sim_sm[(ra + 8) * 16 + m];
#pragma unroll
            for (int nt = 0; nt < 4; nt++) {
                int col = wn * 32 + nt * 8 + 2 * (lane & 3);
                float b0 = bias_sm[m * 128 + col];
                float b1 = bias_sm[m * 128 + col + 1];
                facc[mt][nt][0] += sa * b0;  facc[mt][nt][1] += sa * b1;
                facc[mt][nt][2] += sb_ * b0; facc[mt][nt][3] += sb_ * b1;
            }
        }
    }

    // store
#pragma unroll
    for (int mt = 0; mt < 2; mt++) {
        int ra = brow0 + wm * 32 + mt * 16 + (lane >> 2);
#pragma unroll
        for (int nt = 0; nt < 4; nt++) {
            int col = bcol0 + wn * 32 + nt * 8 + 2 * (lane & 3);
            *reinterpret_cast<float2*>(&out[(size_t)ra * U_SZ + col]) =
                make_float2(facc[mt][nt][0], facc[mt][nt][1]);
            *reinterpret_cast<float2*>(&out[(size_t)(ra + 8) * U_SZ + col]) =
                make_float2(facc[mt][nt][2], facc[mt][nt][3]);
        }
    }
}

// ---------------------------------------------------------------------------
extern "C" void kernel_launch(void* const* d_in, const int* in_sizes, int n_in,
                              void* d_out, int out_size)
{
    const float* x          = (const float*)d_in[0];
    const float* key_kernel = (const float*)d_in[1];
    const float* key_bias   = (const float*)d_in[2];
    const float* keys_map   = (const float*)d_in[3];
    const float* kernels    = (const float*)d_in[4];
    const float* biases     = (const float*)d_in[5];
    float* out = (float*)d_out;

    cudaFuncSetAttribute(pd_mma, cudaFuncAttributeMaxDynamicSharedMemorySize,
                         SMEM_TOTAL);

    conv_x<<<(B_SZ * D_SZ) / (256 * 4), 256>>>(x);
    conv_w<<<dim3(16, 16, 16), dim3(32, 8)>>>(kernels);
    sim_kernel<<<B_SZ / 16, 128>>>(x, key_kernel, key_bias, keys_map);

    dim3 grid(U_SZ / 128, B_SZ / 128);
    pd_mma<<<grid, 512, SMEM_TOTAL>>>(biases, out);
}

// round 7
// speedup vs baseline: 4.4874x; 1.3646x over previous
#include <cuda_runtime.h>
#include <cuda_fp16.h>
#include <cstdint>

#define B_SZ 8192
#define D_SZ 512
#define U_SZ 512
#define M_SZ 16

// ---------------------------------------------------------------------------
// Scratch (static __device__ — no allocations allowed)
// ---------------------------------------------------------------------------
__device__ float  g_sim[B_SZ * M_SZ];          // sim/16
__device__ __half g_xh[B_SZ * D_SZ];
__device__ __half g_wh[M_SZ * U_SZ * D_SZ];    // [m][u][d]  (k-major B)

// ---------------------------------------------------------------------------
// helpers
// ---------------------------------------------------------------------------
__device__ __forceinline__ uint32_t smem_u32(const void* p) {
    uint32_t a;
    asm("{ .reg .u64 t; cvta.to.shared.u64 t, %1; cvt.u32.u64 %0, t; }"
        : "=r"(a) : "l"(p));
    return a;
}
__device__ __forceinline__ void cp_async16(uint32_t saddr, const void* gaddr) {
    asm volatile("cp.async.cg.shared.global [%0], [%1], 16;"
                 :: "r"(saddr), "l"(gaddr) : "memory");
}
__device__ __forceinline__ void ldsm4(uint32_t* r, uint32_t a) {
    asm volatile("ldmatrix.sync.aligned.m8n8.x4.shared.b16 {%0,%1,%2,%3}, [%4];"
                 : "=r"(r[0]), "=r"(r[1]), "=r"(r[2]), "=r"(r[3]) : "r"(a));
}
__device__ __forceinline__ void mma16816(float* c, const uint32_t* a, const uint32_t* b) {
    asm volatile(
        "mma.sync.aligned.m16n8k16.row.col.f32.f16.f16.f32 "
        "{%0,%1,%2,%3}, {%4,%5,%6,%7}, {%8,%9}, {%0,%1,%2,%3};"
        : "+f"(c[0]), "+f"(c[1]), "+f"(c[2]), "+f"(c[3])
        : "r"(a[0]), "r"(a[1]), "r"(a[2]), "r"(a[3]), "r"(b[0]), "r"(b[1]));
}

// ---------------------------------------------------------------------------
// Prep: fp32 -> fp16 of x
// ---------------------------------------------------------------------------
__global__ __launch_bounds__(256) void conv_x(const float* __restrict__ x) {
    size_t i = ((size_t)blockIdx.x * 256 + threadIdx.x) * 4;
    float4 v = *reinterpret_cast<const float4*>(x + i);
    __half2* ph = reinterpret_cast<__half2*>(g_xh + i);
    ph[0] = __halves2half2(__float2half_rn(v.x), __float2half_rn(v.y));
    ph[1] = __halves2half2(__float2half_rn(v.z), __float2half_rn(v.w));
}

// ---------------------------------------------------------------------------
// Prep: kernels [m][d][u] fp32 -> transposed fp16 [m][u][d]
// ---------------------------------------------------------------------------
__global__ __launch_bounds__(256) void conv_w(const float* __restrict__ k) {
    __shared__ float t[32][33];
    int m = blockIdx.z, d0 = blockIdx.x * 32, u0 = blockIdx.y * 32;
    int tx = threadIdx.x, ty = threadIdx.y;
    const float* src = k + (size_t)m * D_SZ * U_SZ;
#pragma unroll
    for (int j = 0; j < 4; j++)
        t[ty + 8 * j][tx] = src[(size_t)(d0 + ty + 8 * j) * U_SZ + u0 + tx];
    __syncthreads();
    size_t ob = (size_t)m * U_SZ * D_SZ;
#pragma unroll
    for (int j = 0; j < 4; j++) {
        float v = t[tx][ty + 8 * j];
        g_wh[ob + (size_t)(u0 + ty + 8 * j) * D_SZ + d0 + tx] = __float2half_rn(v);
    }
}

// ---------------------------------------------------------------------------
// sim kernel v2 — FMA-bound. 32 rows/block, key_kernel staged in smem,
// each thread owns 1 row x 8 k-columns. Stores sim/16.
// ---------------------------------------------------------------------------
#define SIMK_KKS 0                               // [256][64] f32 = 65536 B
#define SIMK_XS  65536                           // [32][260] f32 = 33280 B
#define SIMK_KV  (65536 + 33280)                 // [32][68]  f32 = 8704 B
#define SIMK_SMEM (SIMK_KV + 8704)               // 107520 B

__global__ __launch_bounds__(256) void sim_kernel(
    const float* __restrict__ x, const float* __restrict__ key_kernel,
    const float* __restrict__ key_bias, const float* __restrict__ keys_map)
{
    extern __shared__ __align__(16) char sm[];
    float* kks = reinterpret_cast<float*>(sm + SIMK_KKS);   // [dd][64]
    float* xs  = reinterpret_cast<float*>(sm + SIMK_XS);    // [r][260]
    float* kv  = reinterpret_cast<float*>(sm + SIMK_KV);    // [r][68]

    int tid = threadIdx.x;
    int b0 = blockIdx.x * 32;
    int rl = tid >> 3, kg = tid & 7;

    float acc[8];
#pragma unroll
    for (int j = 0; j < 8; j++) acc[j] = 0.f;

    for (int dt = 0; dt < 2; dt++) {
        // stage key_kernel tile [256 d][64 k]  (4096 float4)
        const float4* kk4 = reinterpret_cast<const float4*>(key_kernel) + dt * 4096;
#pragma unroll
        for (int j = 0; j < 16; j++) {
            int idx = tid + j * 256;           // float4 index
            int dd = idx >> 4, kq = idx & 15;
            *reinterpret_cast<float4*>(&kks[dd * 64 + kq * 4]) = kk4[idx];
        }
        // stage x tile [32 r][256 d]  (2048 float4)
#pragma unroll
        for (int j = 0; j < 8; j++) {
            int idx = tid + j * 256;
            int r = idx >> 6, seg = idx & 63;
            *reinterpret_cast<float4*>(&xs[r * 260 + seg * 4]) =
                reinterpret_cast<const float4*>(x)[(size_t)(b0 + r) * 128 + dt * 64 + seg];
        }
        __syncthreads();

#pragma unroll 4
        for (int dd = 0; dd < 256; dd++) {
            float xv = xs[rl * 260 + dd];
            float4 a = *reinterpret_cast<const float4*>(&kks[dd * 64 + kg * 8]);
            float4 b = *reinterpret_cast<const float4*>(&kks[dd * 64 + kg * 8 + 4]);
            acc[0] += xv * a.x; acc[1] += xv * a.y;
            acc[2] += xv * a.z; acc[3] += xv * a.w;
            acc[4] += xv * b.x; acc[5] += xv * b.y;
            acc[6] += xv * b.z; acc[7] += xv * b.w;
        }
        __syncthreads();
    }

#pragma unroll
    for (int j = 0; j < 8; j++)
        kv[rl * 68 + kg * 8 + j] = acc[j] + key_bias[kg * 8 + j];
    __syncthreads();

    // distances: 32 rows x 16 modes, 2 per thread
    int r = tid >> 3, m0 = tid & 7;
#pragma unroll
    for (int h = 0; h < 2; h++) {
        int m = m0 + h * 8;
        float d2 = 0.f;
#pragma unroll 8
        for (int kk = 0; kk < 64; kk++) {
            float diff = kv[r * 68 + kk] - keys_map[m * 64 + kk];
            d2 += diff * diff;
        }
        g_sim[(b0 + r) * M_SZ + m] = 1.0f / (16.0f * (sqrtf(d2) + 1.0f));
    }
}

// ---------------------------------------------------------------------------
// Main HMMA GEMM. 128x128 tile, BK=32, SINGLE fp16 term, 3-stage cp.async,
// 16 warps (4x4 grid, warp tile 32x32), ONE barrier per iteration,
// mode fold every 16 chunks (sim applied to fp32 partials in registers).
// ---------------------------------------------------------------------------
#define ROWB 80          // padded smem row stride (bytes) for 32 fp16 cols
#define TILEB (128 * ROWB)          // 10240
#define STAGEB (2 * TILEB)          // A | B = 20480
#define SM_BIAS (3 * STAGEB)        // 61440
#define SM_SIM  (SM_BIAS + 16 * 128 * 4)
#define SMEM_TOTAL (SM_SIM + 128 * 16 * 4)   // 77824

__device__ __forceinline__ void issue_loads(
    uint32_t st, int brow0, int bcol0, int m, int d0, int tid)
{
    int row = tid >> 2, seg = tid & 3;           // 512 threads: 1 cp16 per tile
    uint32_t so = (uint32_t)(row * ROWB + seg * 16);
    cp_async16(st + so,
               g_xh + (size_t)(brow0 + row) * D_SZ + d0 + seg * 8);
    cp_async16(st + TILEB + so,
               g_wh + ((size_t)m * U_SZ + bcol0 + row) * D_SZ + d0 + seg * 8);
}

__global__ __launch_bounds__(512, 1) void pd_mma(
    const float* __restrict__ biases, float* __restrict__ out)
{
    extern __shared__ __align__(1024) char smem[];
    uint32_t sb = smem_u32(smem);
    int tid = threadIdx.x;
    int lane = tid & 31, warp = tid >> 5;
    int wm = warp & 3, wn = warp >> 2;     // 4 x 4 warp grid
    int brow0 = blockIdx.y * 128;
    int bcol0 = blockIdx.x * 128;

    float* bias_sm = reinterpret_cast<float*>(smem + SM_BIAS);   // [16][128]
    float* sim_sm  = reinterpret_cast<float*>(smem + SM_SIM);    // [128][16]
    for (int i = tid; i < 16 * 128; i += 512)
        bias_sm[i] = biases[(i >> 7) * U_SZ + bcol0 + (i & 127)];
    for (int i = tid; i < 128 * 16; i += 512)
        sim_sm[i] = g_sim[(brow0 + (i >> 4)) * M_SZ + (i & 15)];

    // ldmatrix smem offsets (relative to stage/tile base)
    uint32_t aoff[2], boff[2];
#pragma unroll
    for (int mt = 0; mt < 2; mt++)
        aoff[mt] = (uint32_t)((wm * 32 + mt * 16 + (lane & 15)) * ROWB +
                              ((lane >> 4) * 16));
#pragma unroll
    for (int p = 0; p < 2; p++)
        boff[p] = (uint32_t)((wn * 32 + p * 16 + ((lane >> 4) * 8) + (lane & 7)) * ROWB +
                             (((lane >> 3) & 1) * 16));

    float macc[2][4][4], facc[2][4][4];
#pragma unroll
    for (int mt = 0; mt < 2; mt++)
#pragma unroll
        for (int nt = 0; nt < 4; nt++)
#pragma unroll
            for (int i = 0; i < 4; i++) { macc[mt][nt][i] = 0.f; facc[mt][nt][i] = 0.f; }

    // prologue: stages 0,1
    issue_loads(sb, brow0, bcol0, 0, 0, tid);
    asm volatile("cp.async.commit_group;" ::: "memory");
    issue_loads(sb + STAGEB, brow0, bcol0, 0, 32, tid);
    asm volatile("cp.async.commit_group;" ::: "memory");

    for (int it = 0; it < 256; it++) {
        // group `it` complete (in-order completion; committed so far: 0..it+1)
        asm volatile("cp.async.wait_group 1;" ::: "memory");
        // visibility of group `it` across threads + all warps finished
        // reading stage (it-1)%3 (ldsm are synchronous register loads)
        __syncthreads();
        int it2 = it + 2;
        if (it2 < 256)
            issue_loads(sb + (it2 % 3) * STAGEB, brow0, bcol0,
                        it2 >> 4, (it2 & 15) * 32, tid);
        asm volatile("cp.async.commit_group;" ::: "memory");

        uint32_t st = sb + (it % 3) * STAGEB;
#pragma unroll
        for (int ks = 0; ks < 2; ks++) {
            uint32_t ah[2][4], bh[2][4];
#pragma unroll
            for (int mt = 0; mt < 2; mt++)
                ldsm4(ah[mt], st + aoff[mt] + ks * 32);
#pragma unroll
            for (int p = 0; p < 2; p++)
                ldsm4(bh[p], st + TILEB + boff[p] + ks * 32);
#pragma unroll
            for (int mt = 0; mt < 2; mt++)
#pragma unroll
                for (int p = 0; p < 2; p++) {
                    mma16816(macc[mt][2 * p],     ah[mt], &bh[p][0]);
                    mma16816(macc[mt][2 * p + 1], ah[mt], &bh[p][2]);
                }
        }

        if ((it & 15) == 15) {        // mode boundary: fold partials
            int m = it >> 4;
#pragma unroll
            for (int mt = 0; mt < 2; mt++) {
                int ra = wm * 32 + mt * 16 + (lane >> 2);
                float sa = sim_sm[ra * 16 + m];
                float sb_ = sim_sm[(ra + 8) * 16 + m];
#pragma unroll
                for (int nt = 0; nt < 4; nt++) {
                    facc[mt][nt][0] += sa  * macc[mt][nt][0];
                    facc[mt][nt][1] += sa  * macc[mt][nt][1];
                    facc[mt][nt][2] += sb_ * macc[mt][nt][2];
                    facc[mt][nt][3] += sb_ * macc[mt][nt][3];
                    macc[mt][nt][0] = 0.f; macc[mt][nt][1] = 0.f;
                    macc[mt][nt][2] = 0.f; macc[mt][nt][3] = 0.f;
                }
            }
        }
    }

    // bias fold:  facc += sum_m (sim/16)[row,m] * biases[m,col]
#pragma unroll
    for (int mt = 0; mt < 2; mt++) {
        int ra = wm * 32 + mt * 16 + (lane >> 2);
        for (int m = 0; m < 16; m++) {
            float sa = sim_sm[ra * 16 + m];
            float sb_ = sim_sm[(ra + 8) * 16 + m];
#pragma unroll
            for (int nt = 0; nt < 4; nt++) {
                int col = wn * 32 + nt * 8 + 2 * (lane & 3);
                float b0 = bias_sm[m * 128 + col];
                float b1 = bias_sm[m * 128 + col + 1];
                facc[mt][nt][0] += sa * b0;  facc[mt][nt][1] += sa * b1;
                facc[mt][nt][2] += sb_ * b0; facc[mt][nt][3] += sb_ * b1;
            }
        }
    }

    // store
#pragma unroll
    for (int mt = 0; mt < 2; mt++) {
        int ra = brow0 + wm * 32 + mt * 16 + (lane >> 2);
#pragma unroll
        for (int nt = 0; nt < 4; nt++) {
            int col = bcol0 + wn * 32 + nt * 8 + 2 * (lane & 3);
            *reinterpret_cast<float2*>(&out[(size_t)ra * U_SZ + col]) =
                make_float2(facc[mt][nt][0], facc[mt][nt][1]);
            *reinterpret_cast<float2*>(&out[(size_t)(ra + 8) * U_SZ + col]) =
                make_float2(facc[mt][nt][2], facc[mt][nt][3]);
        }
    }
}

// ---------------------------------------------------------------------------
extern "C" void kernel_launch(void* const* d_in, const int* in_sizes, int n_in,
                              void* d_out, int out_size)
{
    const float* x          = (const float*)d_in[0];
    const float* key_kernel = (const float*)d_in[1];
    const float* key_bias   = (const float*)d_in[2];
    const float* keys_map   = (const float*)d_in[3];
    const float* kernels    = (const float*)d_in[4];
    const float* biases     = (const float*)d_in[5];
    float* out = (float*)d_out;

    cudaFuncSetAttribute(pd_mma, cudaFuncAttributeMaxDynamicSharedMemorySize,
                         SMEM_TOTAL);
    cudaFuncSetAttribute(sim_kernel, cudaFuncAttributeMaxDynamicSharedMemorySize,
                         SIMK_SMEM);

    conv_x<<<(B_SZ * D_SZ) / (256 * 4), 256>>>(x);
    conv_w<<<dim3(16, 16, 16), dim3(32, 8)>>>(kernels);
    sim_kernel<<<B_SZ / 32, 256, SIMK_SMEM>>>(x, key_kernel, key_bias, keys_map);

    dim3 grid(U_SZ / 128, B_SZ / 128);
    pd_mma<<<grid, 512, SMEM_TOTAL>>>(biases, out);
}

// round 8
// speedup vs baseline: 4.5494x; 1.0138x over previous
#include <cuda_runtime.h>
#include <cuda_fp16.h>
#include <cstdint>

#define B_SZ 8192
#define D_SZ 512
#define U_SZ 512
#define M_SZ 16

// ---------------------------------------------------------------------------
// Scratch (static __device__ — no allocations allowed)
// ---------------------------------------------------------------------------
__device__ float  g_sim[B_SZ * M_SZ];          // sim/16
__device__ __half g_xh[B_SZ * D_SZ];
__device__ __half g_wh[M_SZ * U_SZ * D_SZ];    // [m][u][d]  (k-major B)

// ---------------------------------------------------------------------------
// helpers
// ---------------------------------------------------------------------------
__device__ __forceinline__ uint32_t smem_u32(const void* p) {
    uint32_t a;
    asm("{ .reg .u64 t; cvta.to.shared.u64 t, %1; cvt.u32.u64 %0, t; }"
        : "=r"(a) : "l"(p));
    return a;
}
__device__ __forceinline__ void cp_async16(uint32_t saddr, const void* gaddr) {
    asm volatile("cp.async.cg.shared.global [%0], [%1], 16;"
                 :: "r"(saddr), "l"(gaddr) : "memory");
}
__device__ __forceinline__ void ldsm4(uint32_t* r, uint32_t a) {
    asm volatile("ldmatrix.sync.aligned.m8n8.x4.shared.b16 {%0,%1,%2,%3}, [%4];"
                 : "=r"(r[0]), "=r"(r[1]), "=r"(r[2]), "=r"(r[3]) : "r"(a));
}
__device__ __forceinline__ void mma16816(float* c, const uint32_t* a, const uint32_t* b) {
    asm volatile(
        "mma.sync.aligned.m16n8k16.row.col.f32.f16.f16.f32 "
        "{%0,%1,%2,%3}, {%4,%5,%6,%7}, {%8,%9}, {%0,%1,%2,%3};"
        : "+f"(c[0]), "+f"(c[1]), "+f"(c[2]), "+f"(c[3])
        : "r"(a[0]), "r"(a[1]), "r"(a[2]), "r"(a[3]), "r"(b[0]), "r"(b[1]));
}

// ---------------------------------------------------------------------------
// Unified prep kernel, dispatch on blockIdx.x:
//   blocks [0, 256)        : sim (+ fp16 conversion of x, emitted on the fly)
//   blocks [256, 256+4096) : conv_w (kernels [m][d][u] -> fp16 [m][u][d])
// 256 threads, dynamic smem 58368 B.
// ---------------------------------------------------------------------------
#define PREP_SIM_BLOCKS 256
#define PREP_W_BLOCKS   4096
#define SIMK_KKS 0                               // [128][64] f32 = 32768 B
#define SIMK_XS  32768                           // [32][132] f32 = 16896 B
#define SIMK_KV  (32768 + 16896)                 // [32][68]  f32 =  8704 B
#define PREP_SMEM (SIMK_KV + 8704)               // 58368 B

__global__ __launch_bounds__(256) void prep_kernel(
    const float* __restrict__ x, const float* __restrict__ key_kernel,
    const float* __restrict__ key_bias, const float* __restrict__ keys_map,
    const float* __restrict__ kern)
{
    extern __shared__ __align__(16) char sm[];
    int tid = threadIdx.x;

    if (blockIdx.x >= PREP_SIM_BLOCKS) {
        // ----- conv_w: transpose + fp16 -----
        int bw = blockIdx.x - PREP_SIM_BLOCKS;
        int m = bw >> 8, u0 = ((bw >> 4) & 15) * 32, d0 = (bw & 15) * 32;
        int tx = tid & 31, ty = tid >> 5;
        float* t = reinterpret_cast<float*>(sm);         // [32][33]
        const float* src = kern + (size_t)m * D_SZ * U_SZ;
#pragma unroll
        for (int j = 0; j < 4; j++)
            t[(ty + 8 * j) * 33 + tx] =
                src[(size_t)(d0 + ty + 8 * j) * U_SZ + u0 + tx];
        __syncthreads();
        size_t ob = (size_t)m * U_SZ * D_SZ;
#pragma unroll
        for (int j = 0; j < 4; j++) {
            float v = t[tx * 33 + ty + 8 * j];
            g_wh[ob + (size_t)(u0 + ty + 8 * j) * D_SZ + d0 + tx] =
                __float2half_rn(v);
        }
        return;
    }

    // ----- sim + x fp16 conversion -----
    float* kks = reinterpret_cast<float*>(sm + SIMK_KKS);   // [dd][64]
    float* xs  = reinterpret_cast<float*>(sm + SIMK_XS);    // [r][132]
    float* kv  = reinterpret_cast<float*>(sm + SIMK_KV);    // [r][68]

    int b0 = blockIdx.x * 32;
    int rl = tid >> 3, kg = tid & 7;

    float acc[8];
#pragma unroll
    for (int j = 0; j < 8; j++) acc[j] = 0.f;

    for (int dt = 0; dt < 4; dt++) {
        // stage key_kernel tile [128 d][64 k]  (2048 float4)
        const float4* kk4 = reinterpret_cast<const float4*>(key_kernel) + dt * 2048;
#pragma unroll
        for (int j = 0; j < 8; j++) {
            int idx = tid + j * 256;           // float4 index
            int dd = idx >> 4, kq = idx & 15;
            *reinterpret_cast<float4*>(&kks[dd * 64 + kq * 4]) = kk4[idx];
        }
        // stage x tile [32 r][128 d] (1024 float4) + emit fp16 copy
#pragma unroll
        for (int j = 0; j < 4; j++) {
            int idx = tid + j * 256;
            int r = idx >> 5, seg = idx & 31;
            float4 v = reinterpret_cast<const float4*>(x)
                           [(size_t)(b0 + r) * 128 + dt * 32 + seg];
            *reinterpret_cast<float4*>(&xs[r * 132 + seg * 4]) = v;
            __half2 h0 = __halves2half2(__float2half_rn(v.x), __float2half_rn(v.y));
            __half2 h1 = __halves2half2(__float2half_rn(v.z), __float2half_rn(v.w));
            __half2* dst = reinterpret_cast<__half2*>(
                g_xh + (size_t)(b0 + r) * D_SZ + dt * 128 + seg * 4);
            dst[0] = h0; dst[1] = h1;
        }
        __syncthreads();

#pragma unroll 4
        for (int dd = 0; dd < 128; dd++) {
            float xv = xs[rl * 132 + dt == 4 ? 0 : rl * 132 + dd];  // (guard opt-out)
            xv = xs[rl * 132 + dd];
            float4 a = *reinterpret_cast<const float4*>(&kks[dd * 64 + kg * 8]);
            float4 b = *reinterpret_cast<const float4*>(&kks[dd * 64 + kg * 8 + 4]);
            acc[0] += xv * a.x; acc[1] += xv * a.y;
            acc[2] += xv * a.z; acc[3] += xv * a.w;
            acc[4] += xv * b.x; acc[5] += xv * b.y;
            acc[6] += xv * b.z; acc[7] += xv * b.w;
        }
        __syncthreads();
    }

#pragma unroll
    for (int j = 0; j < 8; j++)
        kv[rl * 68 + kg * 8 + j] = acc[j] + key_bias[kg * 8 + j];
    __syncthreads();

    // distances: 32 rows x 16 modes, 2 per thread
    int r = tid >> 3, m0 = tid & 7;
#pragma unroll
    for (int h = 0; h < 2; h++) {
        int m = m0 + h * 8;
        float d2 = 0.f;
#pragma unroll 8
        for (int kk = 0; kk < 64; kk++) {
            float diff = kv[r * 68 + kk] - keys_map[m * 64 + kk];
            d2 += diff * diff;
        }
        g_sim[(b0 + r) * M_SZ + m] = 1.0f / (16.0f * (sqrtf(d2) + 1.0f));
    }
}

// ---------------------------------------------------------------------------
// Main HMMA GEMM. 128x128 tile, BK=64 per iteration (128 iters), single fp16
// term, 3-stage cp.async, 16 warps (4x4 grid, warp tile 32x32), ONE barrier
// per iteration, mode fold every 8 iterations (fp32 partials in registers).
// ---------------------------------------------------------------------------
#define ROWB 144         // padded smem row stride (bytes) for 64 fp16 cols
#define TILEB (128 * ROWB)          // 18432
#define STAGEB (2 * TILEB)          // A | B = 36864
#define SM_BIAS (3 * STAGEB)        // 110592
#define SM_SIM  (SM_BIAS + 16 * 128 * 4)
#define SMEM_TOTAL (SM_SIM + 128 * 16 * 4)   // 126976

__device__ __forceinline__ void issue_loads(
    uint32_t st, int brow0, int bcol0, int m, int d0, int tid)
{
#pragma unroll
    for (int j = 0; j < 4; j++) {
        int idx = tid + j * 512;            // 2048 chunks of 16B
        int tile = idx >> 10;
        int row = (idx >> 3) & 127;
        int seg = idx & 7;
        uint32_t dst = st + tile * TILEB + (uint32_t)(row * ROWB + seg * 16);
        const __half* g = (tile == 0)
            ? g_xh + (size_t)(brow0 + row) * D_SZ + d0 + seg * 8
            : g_wh + ((size_t)m * U_SZ + bcol0 + row) * D_SZ + d0 + seg * 8;
        cp_async16(dst, g);
    }
}

__global__ __launch_bounds__(512, 1) void pd_mma(
    const float* __restrict__ biases, float* __restrict__ out)
{
    extern __shared__ __align__(1024) char smem[];
    uint32_t sb = smem_u32(smem);
    int tid = threadIdx.x;
    int lane = tid & 31, warp = tid >> 5;
    int wm = warp & 3, wn = warp >> 2;     // 4 x 4 warp grid
    int brow0 = blockIdx.y * 128;
    int bcol0 = blockIdx.x * 128;

    float* bias_sm = reinterpret_cast<float*>(smem + SM_BIAS);   // [16][128]
    float* sim_sm  = reinterpret_cast<float*>(smem + SM_SIM);    // [128][16]
    for (int i = tid; i < 16 * 128; i += 512)
        bias_sm[i] = biases[(i >> 7) * U_SZ + bcol0 + (i & 127)];
    for (int i = tid; i < 128 * 16; i += 512)
        sim_sm[i] = g_sim[(brow0 + (i >> 4)) * M_SZ + (i & 15)];

    // ldmatrix smem offsets (relative to stage/tile base)
    uint32_t aoff[2], boff[2];
#pragma unroll
    for (int mt = 0; mt < 2; mt++)
        aoff[mt] = (uint32_t)((wm * 32 + mt * 16 + (lane & 15)) * ROWB +
                              ((lane >> 4) * 16));
#pragma unroll
    for (int p = 0; p < 2; p++)
        boff[p] = (uint32_t)((wn * 32 + p * 16 + ((lane >> 4) * 8) + (lane & 7)) * ROWB +
                             (((lane >> 3) & 1) * 16));

    float macc[2][4][4], facc[2][4][4];
#pragma unroll
    for (int mt = 0; mt < 2; mt++)
#pragma unroll
        for (int nt = 0; nt < 4; nt++)
#pragma unroll
            for (int i = 0; i < 4; i++) { macc[mt][nt][i] = 0.f; facc[mt][nt][i] = 0.f; }

    // prologue: stages 0,1  (iteration k-span = 64)
    issue_loads(sb, brow0, bcol0, 0, 0, tid);
    asm volatile("cp.async.commit_group;" ::: "memory");
    issue_loads(sb + STAGEB, brow0, bcol0, 0, 64, tid);
    asm volatile("cp.async.commit_group;" ::: "memory");

    for (int it = 0; it < 128; it++) {
        // group `it` complete (in-order completion; committed so far: 0..it+1)
        asm volatile("cp.async.wait_group 1;" ::: "memory");
        // visibility of group `it` across threads + all warps finished
        // reading stage (it-1)%3 (ldsm are synchronous register loads)
        __syncthreads();
        int it2 = it + 2;
        if (it2 < 128)
            issue_loads(sb + (it2 % 3) * STAGEB, brow0, bcol0,
                        it2 >> 3, (it2 & 7) * 64, tid);
        asm volatile("cp.async.commit_group;" ::: "memory");

        uint32_t st = sb + (it % 3) * STAGEB;
#pragma unroll
        for (int ks = 0; ks < 4; ks++) {
            uint32_t ah[2][4], bh[2][4];
#pragma unroll
            for (int mt = 0; mt < 2; mt++)
                ldsm4(ah[mt], st + aoff[mt] + ks * 32);
#pragma unroll
            for (int p = 0; p < 2; p++)
                ldsm4(bh[p], st + TILEB + boff[p] + ks * 32);
#pragma unroll
            for (int mt = 0; mt < 2; mt++)
#pragma unroll
                for (int p = 0; p < 2; p++) {
                    mma16816(macc[mt][2 * p],     ah[mt], &bh[p][0]);
                    mma16816(macc[mt][2 * p + 1], ah[mt], &bh[p][2]);
                }
        }

        if ((it & 7) == 7) {          // mode boundary: fold partials
            int m = it >> 3;
#pragma unroll
            for (int mt = 0; mt < 2; mt++) {
                int ra = wm * 32 + mt * 16 + (lane >> 2);
                float sa = sim_sm[ra * 16 + m];
                float sb_ = sim_sm[(ra + 8) * 16 + m];
#pragma unroll
                for (int nt = 0; nt < 4; nt++) {
                    facc[mt][nt][0] += sa  * macc[mt][nt][0];
                    facc[mt][nt][1] += sa  * macc[mt][nt][1];
                    facc[mt][nt][2] += sb_ * macc[mt][nt][2];
                    facc[mt][nt][3] += sb_ * macc[mt][nt][3];
                    macc[mt][nt][0] = 0.f; macc[mt][nt][1] = 0.f;
                    macc[mt][nt][2] = 0.f; macc[mt][nt][3] = 0.f;
                }
            }
        }
    }

    // bias fold:  facc += sum_m (sim/16)[row,m] * biases[m,col]
#pragma unroll
    for (int mt = 0; mt < 2; mt++) {
        int ra = wm * 32 + mt * 16 + (lane >> 2);
        for (int m = 0; m < 16; m++) {
            float sa = sim_sm[ra * 16 + m];
            float sb_ = sim_sm[(ra + 8) * 16 + m];
#pragma unroll
            for (int nt = 0; nt < 4; nt++) {
                int col = wn * 32 + nt * 8 + 2 * (lane & 3);
                float b0 = bias_sm[m * 128 + col];
                float b1 = bias_sm[m * 128 + col + 1];
                facc[mt][nt][0] += sa * b0;  facc[mt][nt][1] += sa * b1;
                facc[mt][nt][2] += sb_ * b0; facc[mt][nt][3] += sb_ * b1;
            }
        }
    }

    // store
#pragma unroll
    for (int mt = 0; mt < 2; mt++) {
        int ra = brow0 + wm * 32 + mt * 16 + (lane >> 2);
#pragma unroll
        for (int nt = 0; nt < 4; nt++) {
            int col = bcol0 + wn * 32 + nt * 8 + 2 * (lane & 3);
            *reinterpret_cast<float2*>(&out[(size_t)ra * U_SZ + col]) =
                make_float2(facc[mt][nt][0], facc[mt][nt][1]);
            *reinterpret_cast<float2*>(&out[(size_t)(ra + 8) * U_SZ + col]) =
                make_float2(facc[mt][nt][2], facc[mt][nt][3]);
        }
    }
}

// ---------------------------------------------------------------------------
extern "C" void kernel_launch(void* const* d_in, const int* in_sizes, int n_in,
                              void* d_out, int out_size)
{
    const float* x          = (const float*)d_in[0];
    const float* key_kernel = (const float*)d_in[1];
    const float* key_bias   = (const float*)d_in[2];
    const float* keys_map   = (const float*)d_in[3];
    const float* kernels    = (const float*)d_in[4];
    const float* biases     = (const float*)d_in[5];
    float* out = (float*)d_out;

    cudaFuncSetAttribute(pd_mma, cudaFuncAttributeMaxDynamicSharedMemorySize,
                         SMEM_TOTAL);
    cudaFuncSetAttribute(prep_kernel, cudaFuncAttributeMaxDynamicSharedMemorySize,
                         PREP_SMEM);

    prep_kernel<<<PREP_SIM_BLOCKS + PREP_W_BLOCKS, 256, PREP_SMEM>>>(
        x, key_kernel, key_bias, keys_map, kernels);

    dim3 grid(U_SZ / 128, B_SZ / 128);
    pd_mma<<<grid, 512, SMEM_TOTAL>>>(biases, out);
}

// round 9
// speedup vs baseline: 4.5956x; 1.0101x over previous
#include <cuda_runtime.h>
#include <cuda_fp16.h>
#include <cstdint>

#define B_SZ 8192
#define D_SZ 512
#define U_SZ 512
#define M_SZ 16

// ---------------------------------------------------------------------------
// Scratch (static __device__ — no allocations allowed)
// ---------------------------------------------------------------------------
__device__ float  g_sim[B_SZ * M_SZ];          // sim/16
__device__ __half g_xh[B_SZ * D_SZ];           // [b][d]
__device__ __half g_wh[M_SZ * D_SZ * U_SZ];    // [m][d][u]  (natural layout!)

// ---------------------------------------------------------------------------
// helpers
// ---------------------------------------------------------------------------
__device__ __forceinline__ uint32_t smem_u32(const void* p) {
    uint32_t a;
    asm("{ .reg .u64 t; cvta.to.shared.u64 t, %1; cvt.u32.u64 %0, t; }"
        : "=r"(a) : "l"(p));
    return a;
}
__device__ __forceinline__ void cp_async16(uint32_t saddr, const void* gaddr) {
    asm volatile("cp.async.cg.shared.global [%0], [%1], 16;"
                 :: "r"(saddr), "l"(gaddr) : "memory");
}
__device__ __forceinline__ void ldsm4(uint32_t* r, uint32_t a) {
    asm volatile("ldmatrix.sync.aligned.m8n8.x4.shared.b16 {%0,%1,%2,%3}, [%4];"
                 : "=r"(r[0]), "=r"(r[1]), "=r"(r[2]), "=r"(r[3]) : "r"(a));
}
__device__ __forceinline__ void ldsm4t(uint32_t* r, uint32_t a) {
    asm volatile("ldmatrix.sync.aligned.m8n8.x4.trans.shared.b16 {%0,%1,%2,%3}, [%4];"
                 : "=r"(r[0]), "=r"(r[1]), "=r"(r[2]), "=r"(r[3]) : "r"(a));
}
__device__ __forceinline__ void mma16816(float* c, const uint32_t* a, const uint32_t* b) {
    asm volatile(
        "mma.sync.aligned.m16n8k16.row.col.f32.f16.f16.f32 "
        "{%0,%1,%2,%3}, {%4,%5,%6,%7}, {%8,%9}, {%0,%1,%2,%3};"
        : "+f"(c[0]), "+f"(c[1]), "+f"(c[2]), "+f"(c[3])
        : "r"(a[0]), "r"(a[1]), "r"(a[2]), "r"(a[3]), "r"(b[0]), "r"(b[1]));
}

// ---------------------------------------------------------------------------
// Prep 1: streaming fp32 -> fp16 of x AND kernels (both keep natural layout).
// 2048 blocks x 256 threads x 4 float4.
// ---------------------------------------------------------------------------
__global__ __launch_bounds__(256) void conv_stream(
    const float* __restrict__ x, const float* __restrict__ kern)
{
    const uint32_t HALF_N = 1048576u;   // float4 count per array (4.19M floats)
#pragma unroll
    for (int k = 0; k < 4; k++) {
        uint32_t i = blockIdx.x * 1024u + k * 256u + threadIdx.x;
        const float4* src;
        __half2* dst;
        if (i < HALF_N) {
            src = reinterpret_cast<const float4*>(x) + i;
            dst = reinterpret_cast<__half2*>(g_xh) + i * 2;
        } else {
            src = reinterpret_cast<const float4*>(kern) + (i - HALF_N);
            dst = reinterpret_cast<__half2*>(g_wh) + (i - HALF_N) * 2;
        }
        float4 v = *src;
        dst[0] = __halves2half2(__float2half_rn(v.x), __float2half_rn(v.y));
        dst[1] = __halves2half2(__float2half_rn(v.z), __float2half_rn(v.w));
    }
}

// ---------------------------------------------------------------------------
// Prep 2: sim kernel (verified R7) — FMA-bound, stores sim/16.
// ---------------------------------------------------------------------------
#define SIMK_KKS 0                               // [256][64] f32 = 65536 B
#define SIMK_XS  65536                           // [32][260] f32 = 33280 B
#define SIMK_KV  (65536 + 33280)                 // [32][68]  f32 = 8704 B
#define SIMK_SMEM (SIMK_KV + 8704)               // 107520 B

__global__ __launch_bounds__(256) void sim_kernel(
    const float* __restrict__ x, const float* __restrict__ key_kernel,
    const float* __restrict__ key_bias, const float* __restrict__ keys_map)
{
    extern __shared__ __align__(16) char sm[];
    float* kks = reinterpret_cast<float*>(sm + SIMK_KKS);   // [dd][64]
    float* xs  = reinterpret_cast<float*>(sm + SIMK_XS);    // [r][260]
    float* kv  = reinterpret_cast<float*>(sm + SIMK_KV);    // [r][68]

    int tid = threadIdx.x;
    int b0 = blockIdx.x * 32;
    int rl = tid >> 3, kg = tid & 7;

    float acc[8];
#pragma unroll
    for (int j = 0; j < 8; j++) acc[j] = 0.f;

    for (int dt = 0; dt < 2; dt++) {
        const float4* kk4 = reinterpret_cast<const float4*>(key_kernel) + dt * 4096;
#pragma unroll
        for (int j = 0; j < 16; j++) {
            int idx = tid + j * 256;
            int dd = idx >> 4, kq = idx & 15;
            *reinterpret_cast<float4*>(&kks[dd * 64 + kq * 4]) = kk4[idx];
        }
#pragma unroll
        for (int j = 0; j < 8; j++) {
            int idx = tid + j * 256;
            int r = idx >> 6, seg = idx & 63;
            *reinterpret_cast<float4*>(&xs[r * 260 + seg * 4]) =
                reinterpret_cast<const float4*>(x)[(size_t)(b0 + r) * 128 + dt * 64 + seg];
        }
        __syncthreads();

#pragma unroll 4
        for (int dd = 0; dd < 256; dd++) {
            float xv = xs[rl * 260 + dd];
            float4 a = *reinterpret_cast<const float4*>(&kks[dd * 64 + kg * 8]);
            float4 b = *reinterpret_cast<const float4*>(&kks[dd * 64 + kg * 8 + 4]);
            acc[0] += xv * a.x; acc[1] += xv * a.y;
            acc[2] += xv * a.z; acc[3] += xv * a.w;
            acc[4] += xv * b.x; acc[5] += xv * b.y;
            acc[6] += xv * b.z; acc[7] += xv * b.w;
        }
        __syncthreads();
    }

#pragma unroll
    for (int j = 0; j < 8; j++)
        kv[rl * 68 + kg * 8 + j] = acc[j] + key_bias[kg * 8 + j];
    __syncthreads();

    int r = tid >> 3, m0 = tid & 7;
#pragma unroll
    for (int h = 0; h < 2; h++) {
        int m = m0 + h * 8;
        float d2 = 0.f;
#pragma unroll 8
        for (int kk = 0; kk < 64; kk++) {
            float diff = kv[r * 68 + kk] - keys_map[m * 64 + kk];
            d2 += diff * diff;
        }
        g_sim[(b0 + r) * M_SZ + m] = 1.0f / (16.0f * (sqrtf(d2) + 1.0f));
    }
}

// ---------------------------------------------------------------------------
// Main HMMA GEMM. 64x64 tiles (1024 tiles -> near-perfect SM balance),
// 256 threads, 8 warps as 2(m)x4(n), warp tile 32x16, BK=64, 3-stage
// cp.async. B read from NATURAL [m][d][u] layout via ldmatrix.x4.trans.
// Mode fold every 8 iterations (fp32 partials in registers).
// ---------------------------------------------------------------------------
#define RWB 144          // padded smem row stride (bytes) for 64 fp16 cols
#define TILB (64 * RWB)             // 9216
#define STGB (2 * TILB)             // A | B = 18432
#define SM_BIAS (3 * STGB)          // 55296
#define SM_SIM  (SM_BIAS + 16 * 64 * 4)
#define SMEM_TOTAL (SM_SIM + 64 * 16 * 4)    // 63488

__device__ __forceinline__ void issue_loads(
    uint32_t st, int brow0, int bcol0, int m, int d0, int tid)
{
#pragma unroll
    for (int j = 0; j < 4; j++) {
        int idx = tid + j * 256;            // 1024 chunks of 16B
        int tile = idx >> 9;
        int row = (idx >> 3) & 63;
        int seg = idx & 7;
        uint32_t dst = st + tile * TILB + (uint32_t)(row * RWB + seg * 16);
        const __half* g = (tile == 0)
            ? g_xh + (size_t)(brow0 + row) * D_SZ + d0 + seg * 8
            : g_wh + ((size_t)m * D_SZ + d0 + row) * U_SZ + bcol0 + seg * 8;
        cp_async16(dst, g);
    }
}

__global__ __launch_bounds__(256, 2) void pd_mma(
    const float* __restrict__ biases, float* __restrict__ out)
{
    extern __shared__ __align__(1024) char smem[];
    uint32_t sb = smem_u32(smem);
    int tid = threadIdx.x;
    int lane = tid & 31, warp = tid >> 5;
    int wm = warp & 1, wn = warp >> 1;     // 2 x 4 warp grid, warp tile 32x16
    int brow0 = blockIdx.y * 64;           // grid.y = 128
    int bcol0 = blockIdx.x * 64;           // grid.x = 8

    float* bias_sm = reinterpret_cast<float*>(smem + SM_BIAS);   // [16][64]
    float* sim_sm  = reinterpret_cast<float*>(smem + SM_SIM);    // [64][16]
    for (int i = tid; i < 16 * 64; i += 256)
        bias_sm[i] = biases[(i >> 6) * U_SZ + bcol0 + (i & 63)];
    for (int i = tid; i < 64 * 16; i += 256)
        sim_sm[i] = g_sim[(brow0 + (i >> 4)) * M_SZ + (i & 15)];

    // A ldmatrix offsets (rows are m, [m][k] layout, no trans)
    uint32_t aoff[2];
#pragma unroll
    for (int mt = 0; mt < 2; mt++)
        aoff[mt] = (uint32_t)((wm * 32 + mt * 16 + (lane & 15)) * RWB +
                              ((lane >> 4) * 16));
    // B ldmatrix.trans offset ([k][n] natural layout):
    // q = lane>>3 selects matrix: (q&1) = k-half (8 rows), (q>>1) = n-half (8 cols)
    {
    }
    int q = lane >> 3, rr = lane & 7;
    uint32_t boff = (uint32_t)(TILB + ((q & 1) * 8 + rr) * RWB +
                               (wn * 16 + (q >> 1) * 8) * 2);

    float macc[2][2][4], facc[2][2][4];
#pragma unroll
    for (int mt = 0; mt < 2; mt++)
#pragma unroll
        for (int nt = 0; nt < 2; nt++)
#pragma unroll
            for (int i = 0; i < 4; i++) { macc[mt][nt][i] = 0.f; facc[mt][nt][i] = 0.f; }

    // prologue: stages 0,1  (iteration k-span = 64)
    issue_loads(sb, brow0, bcol0, 0, 0, tid);
    asm volatile("cp.async.commit_group;" ::: "memory");
    issue_loads(sb + STGB, brow0, bcol0, 0, 64, tid);
    asm volatile("cp.async.commit_group;" ::: "memory");

    for (int it = 0; it < 128; it++) {
        asm volatile("cp.async.wait_group 1;" ::: "memory");
        __syncthreads();
        int it2 = it + 2;
        if (it2 < 128)
            issue_loads(sb + (it2 % 3) * STGB, brow0, bcol0,
                        it2 >> 3, (it2 & 7) * 64, tid);
        asm volatile("cp.async.commit_group;" ::: "memory");

        uint32_t st = sb + (it % 3) * STGB;
#pragma unroll
        for (int ks = 0; ks < 4; ks++) {
            uint32_t ah[2][4], bf[4];
#pragma unroll
            for (int mt = 0; mt < 2; mt++)
                ldsm4(ah[mt], st + aoff[mt] + ks * 32);
            // B: 16 k-rows x 16 n-cols via x4.trans (k advance = 16 rows)
            ldsm4t(bf, st + boff + ks * 16 * RWB);
            // bf: r0=b0(n0..7), r1=b1(n0..7), r2=b0(n8..15), r3=b1(n8..15)
#pragma unroll
            for (int mt = 0; mt < 2; mt++) {
                mma16816(macc[mt][0], ah[mt], &bf[0]);
                mma16816(macc[mt][1], ah[mt], &bf[2]);
            }
        }

        if ((it & 7) == 7) {          // mode boundary: fold partials
            int m = it >> 3;
#pragma unroll
            for (int mt = 0; mt < 2; mt++) {
                int ra = wm * 32 + mt * 16 + (lane >> 2);
                float sa = sim_sm[ra * 16 + m];
                float sb_ = sim_sm[(ra + 8) * 16 + m];
#pragma unroll
                for (int nt = 0; nt < 2; nt++) {
                    facc[mt][nt][0] += sa  * macc[mt][nt][0];
                    facc[mt][nt][1] += sa  * macc[mt][nt][1];
                    facc[mt][nt][2] += sb_ * macc[mt][nt][2];
                    facc[mt][nt][3] += sb_ * macc[mt][nt][3];
                    macc[mt][nt][0] = 0.f; macc[mt][nt][1] = 0.f;
                    macc[mt][nt][2] = 0.f; macc[mt][nt][3] = 0.f;
                }
            }
        }
    }

    // bias fold:  facc += sum_m (sim/16)[row,m] * biases[m,col]
#pragma unroll
    for (int mt = 0; mt < 2; mt++) {
        int ra = wm * 32 + mt * 16 + (lane >> 2);
        for (int m = 0; m < 16; m++) {
            float sa = sim_sm[ra * 16 + m];
            float sb_ = sim_sm[(ra + 8) * 16 + m];
#pragma unroll
            for (int nt = 0; nt < 2; nt++) {
                int col = wn * 16 + nt * 8 + 2 * (lane & 3);
                float b0 = bias_sm[m * 64 + col];
                float b1 = bias_sm[m * 64 + col + 1];
                facc[mt][nt][0] += sa * b0;  facc[mt][nt][1] += sa * b1;
                facc[mt][nt][2] += sb_ * b0; facc[mt][nt][3] += sb_ * b1;
            }
        }
    }

    // store
#pragma unroll
    for (int mt = 0; mt < 2; mt++) {
        int ra = brow0 + wm * 32 + mt * 16 + (lane >> 2);
#pragma unroll
        for (int nt = 0; nt < 2; nt++) {
            int col = bcol0 + wn * 16 + nt * 8 + 2 * (lane & 3);
            *reinterpret_cast<float2*>(&out[(size_t)ra * U_SZ + col]) =
                make_float2(facc[mt][nt][0], facc[mt][nt][1]);
            *reinterpret_cast<float2*>(&out[(size_t)(ra + 8) * U_SZ + col]) =
                make_float2(facc[mt][nt][2], facc[mt][nt][3]);
        }
    }
}

// ---------------------------------------------------------------------------
extern "C" void kernel_launch(void* const* d_in, const int* in_sizes, int n_in,
                              void* d_out, int out_size)
{
    const float* x          = (const float*)d_in[0];
    const float* key_kernel = (const float*)d_in[1];
    const float* key_bias   = (const float*)d_in[2];
    const float* keys_map   = (const float*)d_in[3];
    const float* kernels    = (const float*)d_in[4];
    const float* biases     = (const float*)d_in[5];
    float* out = (float*)d_out;

    cudaFuncSetAttribute(pd_mma, cudaFuncAttributeMaxDynamicSharedMemorySize,
                         SMEM_TOTAL);
    cudaFuncSetAttribute(sim_kernel, cudaFuncAttributeMaxDynamicSharedMemorySize,
                         SIMK_SMEM);

    conv_stream<<<2048, 256>>>(x, kernels);
    sim_kernel<<<B_SZ / 32, 256, SIMK_SMEM>>>(x, key_kernel, key_bias, keys_map);

    dim3 grid(U_SZ / 64, B_SZ / 64);
    pd_mma<<<grid, 256, SMEM_TOTAL>>>(biases, out);
}

// round 10
// speedup vs baseline: 5.1597x; 1.1228x over previous
#include <cuda_runtime.h>
#include <cuda_fp16.h>
#include <cstdint>

#define B_SZ 8192
#define D_SZ 512
#define U_SZ 512
#define M_SZ 16

// ---------------------------------------------------------------------------
// Scratch (static __device__ — no allocations allowed)
// ---------------------------------------------------------------------------
__device__ float  g_sim[B_SZ * M_SZ];          // sim/16
__device__ __half g_xh[B_SZ * D_SZ];           // [b][d]
__device__ __half g_wh[M_SZ * U_SZ * D_SZ];    // [m][u][d]  (k-major B)

// ---------------------------------------------------------------------------
// helpers
// ---------------------------------------------------------------------------
__device__ __forceinline__ uint32_t smem_u32(const void* p) {
    uint32_t a;
    asm("{ .reg .u64 t; cvta.to.shared.u64 t, %1; cvt.u32.u64 %0, t; }"
        : "=r"(a) : "l"(p));
    return a;
}
__device__ __forceinline__ void cp_async16(uint32_t saddr, const void* gaddr) {
    asm volatile("cp.async.cg.shared.global [%0], [%1], 16;"
                 :: "r"(saddr), "l"(gaddr) : "memory");
}
__device__ __forceinline__ void ldsm4(uint32_t* r, uint32_t a) {
    asm volatile("ldmatrix.sync.aligned.m8n8.x4.shared.b16 {%0,%1,%2,%3}, [%4];"
                 : "=r"(r[0]), "=r"(r[1]), "=r"(r[2]), "=r"(r[3]) : "r"(a));
}
__device__ __forceinline__ void mma16816(float* c, const uint32_t* a, const uint32_t* b) {
    asm volatile(
        "mma.sync.aligned.m16n8k16.row.col.f32.f16.f16.f32 "
        "{%0,%1,%2,%3}, {%4,%5,%6,%7}, {%8,%9}, {%0,%1,%2,%3};"
        : "+f"(c[0]), "+f"(c[1]), "+f"(c[2]), "+f"(c[3])
        : "r"(a[0]), "r"(a[1]), "r"(a[2]), "r"(a[3]), "r"(b[0]), "r"(b[1]));
}

// ---------------------------------------------------------------------------
// zero-init of out (harness poisons it; atomic epilogue needs zeros)
// ---------------------------------------------------------------------------
__global__ __launch_bounds__(512) void zero_out(float4* __restrict__ o) {
    o[blockIdx.x * 512u + threadIdx.x] = make_float4(0.f, 0.f, 0.f, 0.f);
}

// ---------------------------------------------------------------------------
// Prep 1: streaming fp32 -> fp16 of x (natural) — W needs transpose (below)
// ---------------------------------------------------------------------------
__global__ __launch_bounds__(256) void conv_x(const float* __restrict__ x) {
    size_t i = ((size_t)blockIdx.x * 256 + threadIdx.x) * 4;
    float4 v = *reinterpret_cast<const float4*>(x + i);
    __half2* ph = reinterpret_cast<__half2*>(g_xh + i);
    ph[0] = __halves2half2(__float2half_rn(v.x), __float2half_rn(v.y));
    ph[1] = __halves2half2(__float2half_rn(v.z), __float2half_rn(v.w));
}

// ---------------------------------------------------------------------------
// Prep 2: kernels [m][d][u] fp32 -> transposed fp16 [m][u][d]  (verified R6)
// ---------------------------------------------------------------------------
__global__ __launch_bounds__(256) void conv_w(const float* __restrict__ k) {
    __shared__ float t[32][33];
    int m = blockIdx.z, d0 = blockIdx.x * 32, u0 = blockIdx.y * 32;
    int tx = threadIdx.x, ty = threadIdx.y;
    const float* src = k + (size_t)m * D_SZ * U_SZ;
#pragma unroll
    for (int j = 0; j < 4; j++)
        t[ty + 8 * j][tx] = src[(size_t)(d0 + ty + 8 * j) * U_SZ + u0 + tx];
    __syncthreads();
    size_t ob = (size_t)m * U_SZ * D_SZ;
#pragma unroll
    for (int j = 0; j < 4; j++) {
        float v = t[tx][ty + 8 * j];
        g_wh[ob + (size_t)(u0 + ty + 8 * j) * D_SZ + d0 + tx] = __float2half_rn(v);
    }
}

// ---------------------------------------------------------------------------
// Prep 3: sim kernel (verified R7/R9) — FMA-bound, stores sim/16.
// ---------------------------------------------------------------------------
#define SIMK_KKS 0                               // [256][64] f32 = 65536 B
#define SIMK_XS  65536                           // [32][260] f32 = 33280 B
#define SIMK_KV  (65536 + 33280)                 // [32][68]  f32 = 8704 B
#define SIMK_SMEM (SIMK_KV + 8704)               // 107520 B

__global__ __launch_bounds__(256) void sim_kernel(
    const float* __restrict__ x, const float* __restrict__ key_kernel,
    const float* __restrict__ key_bias, const float* __restrict__ keys_map)
{
    extern __shared__ __align__(16) char sm[];
    float* kks = reinterpret_cast<float*>(sm + SIMK_KKS);   // [dd][64]
    float* xs  = reinterpret_cast<float*>(sm + SIMK_XS);    // [r][260]
    float* kv  = reinterpret_cast<float*>(sm + SIMK_KV);    // [r][68]

    int tid = threadIdx.x;
    int b0 = blockIdx.x * 32;
    int rl = tid >> 3, kg = tid & 7;

    float acc[8];
#pragma unroll
    for (int j = 0; j < 8; j++) acc[j] = 0.f;

    for (int dt = 0; dt < 2; dt++) {
        const float4* kk4 = reinterpret_cast<const float4*>(key_kernel) + dt * 4096;
#pragma unroll
        for (int j = 0; j < 16; j++) {
            int idx = tid + j * 256;
            int dd = idx >> 4, kq = idx & 15;
            *reinterpret_cast<float4*>(&kks[dd * 64 + kq * 4]) = kk4[idx];
        }
#pragma unroll
        for (int j = 0; j < 8; j++) {
            int idx = tid + j * 256;
            int r = idx >> 6, seg = idx & 63;
            *reinterpret_cast<float4*>(&xs[r * 260 + seg * 4]) =
                reinterpret_cast<const float4*>(x)[(size_t)(b0 + r) * 128 + dt * 64 + seg];
        }
        __syncthreads();

#pragma unroll 4
        for (int dd = 0; dd < 256; dd++) {
            float xv = xs[rl * 260 + dd];
            float4 a = *reinterpret_cast<const float4*>(&kks[dd * 64 + kg * 8]);
            float4 b = *reinterpret_cast<const float4*>(&kks[dd * 64 + kg * 8 + 4]);
            acc[0] += xv * a.x; acc[1] += xv * a.y;
            acc[2] += xv * a.z; acc[3] += xv * a.w;
            acc[4] += xv * b.x; acc[5] += xv * b.y;
            acc[6] += xv * b.z; acc[7] += xv * b.w;
        }
        __syncthreads();
    }

#pragma unroll
    for (int j = 0; j < 8; j++)
        kv[rl * 68 + kg * 8 + j] = acc[j] + key_bias[kg * 8 + j];
    __syncthreads();

    int r = tid >> 3, m0 = tid & 7;
#pragma unroll
    for (int h = 0; h < 2; h++) {
        int m = m0 + h * 8;
        float d2 = 0.f;
#pragma unroll 8
        for (int kk = 0; kk < 64; kk++) {
            float diff = kv[r * 68 + kk] - keys_map[m * 64 + kk];
            d2 += diff * diff;
        }
        g_sim[(b0 + r) * M_SZ + m] = 1.0f / (16.0f * (sqrtf(d2) + 1.0f));
    }
}

// ---------------------------------------------------------------------------
// Main HMMA GEMM — R8's verified 128x128/BK=64 mainloop, SPLIT-K x4.
// grid = (4, 64, 4): (col-tile, row-tile, k-split). Each CTA runs global
// iterations [32s, 32s+32) = modes [4s, 4s+4), folds sim-weighted partials
// in registers, and accumulates into out via atomicAdd (out pre-zeroed).
// ---------------------------------------------------------------------------
#define ROWB 144         // padded smem row stride (bytes) for 64 fp16 cols
#define TILEB (128 * ROWB)          // 18432
#define STAGEB (2 * TILEB)          // A | B = 36864
#define SM_BIAS (3 * STAGEB)        // 110592
#define SM_SIM  (SM_BIAS + 16 * 128 * 4)
#define SMEM_TOTAL (SM_SIM + 128 * 16 * 4)   // 126976

__device__ __forceinline__ void issue_loads(
    uint32_t st, int brow0, int bcol0, int m, int d0, int tid)
{
#pragma unroll
    for (int j = 0; j < 4; j++) {
        int idx = tid + j * 512;            // 2048 chunks of 16B
        int tile = idx >> 10;
        int row = (idx >> 3) & 127;
        int seg = idx & 7;
        uint32_t dst = st + tile * TILEB + (uint32_t)(row * ROWB + seg * 16);
        const __half* g = (tile == 0)
            ? g_xh + (size_t)(brow0 + row) * D_SZ + d0 + seg * 8
            : g_wh + ((size_t)m * U_SZ + bcol0 + row) * D_SZ + d0 + seg * 8;
        cp_async16(dst, g);
    }
}

__global__ __launch_bounds__(512, 1) void pd_mma(
    const float* __restrict__ biases, float* __restrict__ out)
{
    extern __shared__ __align__(1024) char smem[];
    uint32_t sb = smem_u32(smem);
    int tid = threadIdx.x;
    int lane = tid & 31, warp = tid >> 5;
    int wm = warp & 3, wn = warp >> 2;     // 4 x 4 warp grid
    int brow0 = blockIdx.y * 128;
    int bcol0 = blockIdx.x * 128;
    int split = blockIdx.z;                // 0..3
    int gbase = split * 32;                // global iteration base

    float* bias_sm = reinterpret_cast<float*>(smem + SM_BIAS);   // [16][128]
    float* sim_sm  = reinterpret_cast<float*>(smem + SM_SIM);    // [128][16]
    for (int i = tid; i < 16 * 128; i += 512)
        bias_sm[i] = biases[(i >> 7) * U_SZ + bcol0 + (i & 127)];
    for (int i = tid; i < 128 * 16; i += 512)
        sim_sm[i] = g_sim[(brow0 + (i >> 4)) * M_SZ + (i & 15)];

    // ldmatrix smem offsets (verified R8)
    uint32_t aoff[2], boff[2];
#pragma unroll
    for (int mt = 0; mt < 2; mt++)
        aoff[mt] = (uint32_t)((wm * 32 + mt * 16 + (lane & 15)) * ROWB +
                              ((lane >> 4) * 16));
#pragma unroll
    for (int p = 0; p < 2; p++)
        boff[p] = (uint32_t)((wn * 32 + p * 16 + ((lane >> 4) * 8) + (lane & 7)) * ROWB +
                             (((lane >> 3) & 1) * 16));

    float macc[2][4][4], facc[2][4][4];
#pragma unroll
    for (int mt = 0; mt < 2; mt++)
#pragma unroll
        for (int nt = 0; nt < 4; nt++)
#pragma unroll
            for (int i = 0; i < 4; i++) { macc[mt][nt][i] = 0.f; facc[mt][nt][i] = 0.f; }

    // prologue: stages 0,1  (global iterations gbase, gbase+1)
    issue_loads(sb, brow0, bcol0, gbase >> 3, (gbase & 7) * 64, tid);
    asm volatile("cp.async.commit_group;" ::: "memory");
    issue_loads(sb + STAGEB, brow0, bcol0, (gbase + 1) >> 3, ((gbase + 1) & 7) * 64, tid);
    asm volatile("cp.async.commit_group;" ::: "memory");

    for (int it = 0; it < 32; it++) {
        asm volatile("cp.async.wait_group 1;" ::: "memory");
        __syncthreads();
        int it2 = it + 2;
        if (it2 < 32) {
            int g2 = gbase + it2;
            issue_loads(sb + (it2 % 3) * STAGEB, brow0, bcol0,
                        g2 >> 3, (g2 & 7) * 64, tid);
        }
        asm volatile("cp.async.commit_group;" ::: "memory");

        uint32_t st = sb + (it % 3) * STAGEB;
#pragma unroll
        for (int ks = 0; ks < 4; ks++) {
            uint32_t ah[2][4], bh[2][4];
#pragma unroll
            for (int mt = 0; mt < 2; mt++)
                ldsm4(ah[mt], st + aoff[mt] + ks * 32);
#pragma unroll
            for (int p = 0; p < 2; p++)
                ldsm4(bh[p], st + TILEB + boff[p] + ks * 32);
#pragma unroll
            for (int mt = 0; mt < 2; mt++)
#pragma unroll
                for (int p = 0; p < 2; p++) {
                    mma16816(macc[mt][2 * p],     ah[mt], &bh[p][0]);
                    mma16816(macc[mt][2 * p + 1], ah[mt], &bh[p][2]);
                }
        }

        if ((it & 7) == 7) {          // mode boundary: fold partials
            int m = (gbase + it) >> 3;
#pragma unroll
            for (int mt = 0; mt < 2; mt++) {
                int ra = wm * 32 + mt * 16 + (lane >> 2);
                float sa = sim_sm[ra * 16 + m];
                float sb_ = sim_sm[(ra + 8) * 16 + m];
#pragma unroll
                for (int nt = 0; nt < 4; nt++) {
                    facc[mt][nt][0] += sa  * macc[mt][nt][0];
                    facc[mt][nt][1] += sa  * macc[mt][nt][1];
                    facc[mt][nt][2] += sb_ * macc[mt][nt][2];
                    facc[mt][nt][3] += sb_ * macc[mt][nt][3];
                    macc[mt][nt][0] = 0.f; macc[mt][nt][1] = 0.f;
                    macc[mt][nt][2] = 0.f; macc[mt][nt][3] = 0.f;
                }
            }
        }
    }

    // bias fold (split 0 only):  facc += sum_m (sim/16)[row,m] * biases[m,col]
    if (split == 0) {
#pragma unroll
        for (int mt = 0; mt < 2; mt++) {
            int ra = wm * 32 + mt * 16 + (lane >> 2);
            for (int m = 0; m < 16; m++) {
                float sa = sim_sm[ra * 16 + m];
                float sb_ = sim_sm[(ra + 8) * 16 + m];
#pragma unroll
                for (int nt = 0; nt < 4; nt++) {
                    int col = wn * 32 + nt * 8 + 2 * (lane & 3);
                    float b0 = bias_sm[m * 128 + col];
                    float b1 = bias_sm[m * 128 + col + 1];
                    facc[mt][nt][0] += sa * b0;  facc[mt][nt][1] += sa * b1;
                    facc[mt][nt][2] += sb_ * b0; facc[mt][nt][3] += sb_ * b1;
                }
            }
        }
    }

    // accumulate into out (pre-zeroed)
#pragma unroll
    for (int mt = 0; mt < 2; mt++) {
        int ra = brow0 + wm * 32 + mt * 16 + (lane >> 2);
#pragma unroll
        for (int nt = 0; nt < 4; nt++) {
            int col = bcol0 + wn * 32 + nt * 8 + 2 * (lane & 3);
            atomicAdd(&out[(size_t)ra * U_SZ + col],       facc[mt][nt][0]);
            atomicAdd(&out[(size_t)ra * U_SZ + col + 1],   facc[mt][nt][1]);
            atomicAdd(&out[(size_t)(ra + 8) * U_SZ + col],     facc[mt][nt][2]);
            atomicAdd(&out[(size_t)(ra + 8) * U_SZ + col + 1], facc[mt][nt][3]);
        }
    }
}

// ---------------------------------------------------------------------------
extern "C" void kernel_launch(void* const* d_in, const int* in_sizes, int n_in,
                              void* d_out, int out_size)
{
    const float* x          = (const float*)d_in[0];
    const float* key_kernel = (const float*)d_in[1];
    const float* key_bias   = (const float*)d_in[2];
    const float* keys_map   = (const float*)d_in[3];
    const float* kernels    = (const float*)d_in[4];
    const float* biases     = (const float*)d_in[5];
    float* out = (float*)d_out;

    cudaFuncSetAttribute(pd_mma, cudaFuncAttributeMaxDynamicSharedMemorySize,
                         SMEM_TOTAL);
    cudaFuncSetAttribute(sim_kernel, cudaFuncAttributeMaxDynamicSharedMemorySize,
                         SIMK_SMEM);

    zero_out<<<(B_SZ * U_SZ) / (512 * 4), 512>>>((float4*)out);
    conv_x<<<(B_SZ * D_SZ) / (256 * 4), 256>>>(x);
    conv_w<<<dim3(16, 16, 16), dim3(32, 8)>>>(kernels);
    sim_kernel<<<B_SZ / 32, 256, SIMK_SMEM>>>(x, key_kernel, key_bias, keys_map);

    dim3 grid(U_SZ / 128, B_SZ / 128, 4);
    pd_mma<<<grid, 512, SMEM_TOTAL>>>(biases, out);
}

// round 11
// speedup vs baseline: 6.3436x; 1.2295x over previous
#include <cuda_runtime.h>
#include <cuda_fp16.h>
#include <cstdint>

#define B_SZ 8192
#define D_SZ 512
#define U_SZ 512
#define M_SZ 16

// ---------------------------------------------------------------------------
// Scratch (static __device__ — no allocations allowed)
// ---------------------------------------------------------------------------
__device__ float  g_sim[B_SZ * M_SZ];          // sim/16
__device__ __half g_xh[B_SZ * D_SZ];           // [b][d]
__device__ __half g_wh[M_SZ * U_SZ * D_SZ];    // [m][u][d]  (k-major B)

// ---------------------------------------------------------------------------
// helpers
// ---------------------------------------------------------------------------
__device__ __forceinline__ uint32_t smem_u32(const void* p) {
    uint32_t a;
    asm("{ .reg .u64 t; cvta.to.shared.u64 t, %1; cvt.u32.u64 %0, t; }"
        : "=r"(a) : "l"(p));
    return a;
}
__device__ __forceinline__ void cp_async16(uint32_t saddr, const void* gaddr) {
    asm volatile("cp.async.cg.shared.global [%0], [%1], 16;"
                 :: "r"(saddr), "l"(gaddr) : "memory");
}
__device__ __forceinline__ void ldsm4(uint32_t* r, uint32_t a) {
    asm volatile("ldmatrix.sync.aligned.m8n8.x4.shared.b16 {%0,%1,%2,%3}, [%4];"
                 : "=r"(r[0]), "=r"(r[1]), "=r"(r[2]), "=r"(r[3]) : "r"(a));
}
__device__ __forceinline__ void ldsm4t(uint32_t* r, uint32_t a) {
    asm volatile("ldmatrix.sync.aligned.m8n8.x4.trans.shared.b16 {%0,%1,%2,%3}, [%4];"
                 : "=r"(r[0]), "=r"(r[1]), "=r"(r[2]), "=r"(r[3]) : "r"(a));
}
__device__ __forceinline__ void mma16816(float* c, const uint32_t* a, const uint32_t* b) {
    asm volatile(
        "mma.sync.aligned.m16n8k16.row.col.f32.f16.f16.f32 "
        "{%0,%1,%2,%3}, {%4,%5,%6,%7}, {%8,%9}, {%0,%1,%2,%3};"
        : "+f"(c[0]), "+f"(c[1]), "+f"(c[2]), "+f"(c[3])
        : "r"(a[0]), "r"(a[1]), "r"(a[2]), "r"(a[3]), "r"(b[0]), "r"(b[1]));
}

// ---------------------------------------------------------------------------
// zero-init of out (harness poisons it; atomic epilogue needs zeros)
// ---------------------------------------------------------------------------
__global__ __launch_bounds__(512) void zero_out(float4* __restrict__ o) {
    o[blockIdx.x * 512u + threadIdx.x] = make_float4(0.f, 0.f, 0.f, 0.f);
}

// ---------------------------------------------------------------------------
// Prep 1: streaming fp32 -> fp16 of x
// ---------------------------------------------------------------------------
__global__ __launch_bounds__(256) void conv_x(const float* __restrict__ x) {
    size_t i = ((size_t)blockIdx.x * 256 + threadIdx.x) * 4;
    float4 v = *reinterpret_cast<const float4*>(x + i);
    __half2* ph = reinterpret_cast<__half2*>(g_xh + i);
    ph[0] = __halves2half2(__float2half_rn(v.x), __float2half_rn(v.y));
    ph[1] = __halves2half2(__float2half_rn(v.z), __float2half_rn(v.w));
}

// ---------------------------------------------------------------------------
// Prep 2: kernels [m][d][u] fp32 -> transposed fp16 [m][u][d]  (verified R6)
// ---------------------------------------------------------------------------
__global__ __launch_bounds__(256) void conv_w(const float* __restrict__ k) {
    __shared__ float t[32][33];
    int m = blockIdx.z, d0 = blockIdx.x * 32, u0 = blockIdx.y * 32;
    int tx = threadIdx.x, ty = threadIdx.y;
    const float* src = k + (size_t)m * D_SZ * U_SZ;
#pragma unroll
    for (int j = 0; j < 4; j++)
        t[ty + 8 * j][tx] = src[(size_t)(d0 + ty + 8 * j) * U_SZ + u0 + tx];
    __syncthreads();
    size_t ob = (size_t)m * U_SZ * D_SZ;
#pragma unroll
    for (int j = 0; j < 4; j++) {
        float v = t[tx][ty + 8 * j];
        g_wh[ob + (size_t)(u0 + ty + 8 * j) * D_SZ + d0 + tx] = __float2half_rn(v);
    }
}

// ---------------------------------------------------------------------------
// Prep 3: keyv via HMMA + fused distances -> g_sim (sim/16).
// 64 blocks x 256 threads. Each block: 128 rows.
//   keyv[128,64] = g_xh[rows,512] @ key_kernel_fp16[512,64] (+bias)
// A: 3-stage cp.async (verified pattern). B: ldsm4t from natural [k][n]
// (R9-verified mapping, 144B row stride). Dist epilogue scalar.
// ---------------------------------------------------------------------------
#define KV_KKH 0                      // half [512][72] = 73728
#define KV_A   73728                  // 3 x (128*144) = 55296  (reused for kv f32)
#define KV_KM  129024                 // f32 [16][65] = 4160
#define KV_BS  133184                 // f32 [64] = 256
#define KV_SMEM 133440

__global__ __launch_bounds__(256) void keyv_sim(
    const float* __restrict__ key_kernel, const float* __restrict__ key_bias,
    const float* __restrict__ keys_map)
{
    extern __shared__ __align__(1024) char sm[];
    uint32_t sb = smem_u32(sm);
    int tid = threadIdx.x;
    int lane = tid & 31, w = tid >> 5;           // 8 warps x 16 rows
    int b0 = blockIdx.x * 128;

    // stage key_kernel fp32 -> fp16 [512][72-pad]
    const float4* kk4 = reinterpret_cast<const float4*>(key_kernel);
#pragma unroll
    for (int j = 0; j < 32; j++) {
        int i = tid + j * 256;                   // 8192 float4
        int row = i >> 4, c4 = (i & 15) * 4;
        float4 v = kk4[i];
        __half2* dst = reinterpret_cast<__half2*>(sm + KV_KKH + row * 144 + c4 * 2);
        dst[0] = __halves2half2(__float2half_rn(v.x), __float2half_rn(v.y));
        dst[1] = __halves2half2(__float2half_rn(v.z), __float2half_rn(v.w));
    }
    // stage keys_map (pad 65) + bias
    float* kmf = reinterpret_cast<float*>(sm + KV_KM);
    float* bs  = reinterpret_cast<float*>(sm + KV_BS);
#pragma unroll
    for (int j = 0; j < 4; j++) {
        int i = tid + j * 256;
        kmf[(i >> 6) * 65 + (i & 63)] = keys_map[i];
    }
    if (tid < 64) bs[tid] = key_bias[tid];

    // A chunk loader: 128 rows x 64 halves (16KB), 4 cp16/thread
    auto issue_A = [&](uint32_t st, int kc) {
#pragma unroll
        for (int j = 0; j < 4; j++) {
            int idx = tid + j * 256;
            int row = idx >> 3, seg = idx & 7;
            cp_async16(st + (uint32_t)(row * 144 + seg * 16),
                       g_xh + (size_t)(b0 + row) * D_SZ + kc * 64 + seg * 8);
        }
    };

    float acc[8][4];
#pragma unroll
    for (int j = 0; j < 8; j++)
#pragma unroll
        for (int i = 0; i < 4; i++) acc[j][i] = 0.f;

    issue_A(sb + KV_A, 0);
    asm volatile("cp.async.commit_group;" ::: "memory");
    issue_A(sb + KV_A + 18432, 1);
    asm volatile("cp.async.commit_group;" ::: "memory");

    int q = lane >> 3, rr = lane & 7;
    uint32_t aoffb = (uint32_t)((w * 16 + (lane & 15)) * 144 + (lane >> 4) * 16);
    uint32_t boffb = (uint32_t)(KV_KKH + ((q & 1) * 8 + rr) * 144 + ((q >> 1) * 8) * 2);

    for (int kc = 0; kc < 8; kc++) {
        asm volatile("cp.async.wait_group 1;" ::: "memory");
        __syncthreads();     // group kc visible; also covers kkh/km staging (kc=0)
        int k2 = kc + 2;
        if (k2 < 8) issue_A(sb + KV_A + (k2 % 3) * 18432, k2);
        asm volatile("cp.async.commit_group;" ::: "memory");

        uint32_t ab = sb + KV_A + (kc % 3) * 18432;
#pragma unroll
        for (int ks = 0; ks < 4; ks++) {
            uint32_t ah[4], bf[4][4];
            ldsm4(ah, ab + aoffb + ks * 32);
            uint32_t kb = sb + boffb + (uint32_t)((kc * 64 + ks * 16) * 144);
#pragma unroll
            for (int p = 0; p < 4; p++)
                ldsm4t(bf[p], kb + p * 32);
#pragma unroll
            for (int p = 0; p < 4; p++) {
                mma16816(acc[2 * p],     ah, &bf[p][0]);
                mma16816(acc[2 * p + 1], ah, &bf[p][2]);
            }
        }
    }

    // write keyv (+bias) to smem (reuse A region), then distances
    __syncthreads();                      // all ldsm reads of A buffers done
    float* kvs = reinterpret_cast<float*>(sm + KV_A);    // [128][68]
    {
        int r0 = w * 16 + (lane >> 2);
        int c0 = 2 * (lane & 3);
#pragma unroll
        for (int j = 0; j < 8; j++) {
            int col = j * 8 + c0;
            kvs[r0 * 68 + col]           = acc[j][0] + bs[col];
            kvs[r0 * 68 + col + 1]       = acc[j][1] + bs[col + 1];
            kvs[(r0 + 8) * 68 + col]     = acc[j][2] + bs[col];
            kvs[(r0 + 8) * 68 + col + 1] = acc[j][3] + bs[col + 1];
        }
    }
    __syncthreads();

#pragma unroll
    for (int i = 0; i < 8; i++) {
        int task = tid + i * 256;          // 2048 = 128 rows x 16 modes
        int row = task >> 4, mode = task & 15;
        float d2 = 0.f;
#pragma unroll 8
        for (int kk = 0; kk < 64; kk++) {
            float diff = kvs[row * 68 + kk] - kmf[mode * 65 + kk];
            d2 += diff * diff;
        }
        g_sim[(size_t)(b0 + row) * M_SZ + mode] =
            1.0f / (16.0f * (sqrtf(d2) + 1.0f));
    }
}

// ---------------------------------------------------------------------------
// Main HMMA GEMM — R8's verified 128x128/BK=64 mainloop, SPLIT-K x4 (R10).
// ---------------------------------------------------------------------------
#define ROWB 144
#define TILEB (128 * ROWB)          // 18432
#define STAGEB (2 * TILEB)          // 36864
#define SM_BIAS (3 * STAGEB)        // 110592
#define SM_SIM  (SM_BIAS + 16 * 128 * 4)
#define SMEM_TOTAL (SM_SIM + 128 * 16 * 4)   // 126976

__device__ __forceinline__ void issue_loads(
    uint32_t st, int brow0, int bcol0, int m, int d0, int tid)
{
#pragma unroll
    for (int j = 0; j < 4; j++) {
        int idx = tid + j * 512;
        int tile = idx >> 10;
        int row = (idx >> 3) & 127;
        int seg = idx & 7;
        uint32_t dst = st + tile * TILEB + (uint32_t)(row * ROWB + seg * 16);
        const __half* g = (tile == 0)
            ? g_xh + (size_t)(brow0 + row) * D_SZ + d0 + seg * 8
            : g_wh + ((size_t)m * U_SZ + bcol0 + row) * D_SZ + d0 + seg * 8;
        cp_async16(dst, g);
    }
}

__global__ __launch_bounds__(512, 1) void pd_mma(
    const float* __restrict__ biases, float* __restrict__ out)
{
    extern __shared__ __align__(1024) char smem[];
    uint32_t sb = smem_u32(smem);
    int tid = threadIdx.x;
    int lane = tid & 31, warp = tid >> 5;
    int wm = warp & 3, wn = warp >> 2;
    int brow0 = blockIdx.y * 128;
    int bcol0 = blockIdx.x * 128;
    int split = blockIdx.z;
    int gbase = split * 32;

    float* bias_sm = reinterpret_cast<float*>(smem + SM_BIAS);
    float* sim_sm  = reinterpret_cast<float*>(smem + SM_SIM);
    for (int i = tid; i < 16 * 128; i += 512)
        bias_sm[i] = biases[(i >> 7) * U_SZ + bcol0 + (i & 127)];
    for (int i = tid; i < 128 * 16; i += 512)
        sim_sm[i] = g_sim[(brow0 + (i >> 4)) * M_SZ + (i & 15)];

    uint32_t aoff[2], boff[2];
#pragma unroll
    for (int mt = 0; mt < 2; mt++)
        aoff[mt] = (uint32_t)((wm * 32 + mt * 16 + (lane & 15)) * ROWB +
                              ((lane >> 4) * 16));
#pragma unroll
    for (int p = 0; p < 2; p++)
        boff[p] = (uint32_t)((wn * 32 + p * 16 + ((lane >> 4) * 8) + (lane & 7)) * ROWB +
                             (((lane >> 3) & 1) * 16));

    float macc[2][4][4], facc[2][4][4];
#pragma unroll
    for (int mt = 0; mt < 2; mt++)
#pragma unroll
        for (int nt = 0; nt < 4; nt++)
#pragma unroll
            for (int i = 0; i < 4; i++) { macc[mt][nt][i] = 0.f; facc[mt][nt][i] = 0.f; }

    issue_loads(sb, brow0, bcol0, gbase >> 3, (gbase & 7) * 64, tid);
    asm volatile("cp.async.commit_group;" ::: "memory");
    issue_loads(sb + STAGEB, brow0, bcol0, (gbase + 1) >> 3, ((gbase + 1) & 7) * 64, tid);
    asm volatile("cp.async.commit_group;" ::: "memory");

    for (int it = 0; it < 32; it++) {
        asm volatile("cp.async.wait_group 1;" ::: "memory");
        __syncthreads();
        int it2 = it + 2;
        if (it2 < 32) {
            int g2 = gbase + it2;
            issue_loads(sb + (it2 % 3) * STAGEB, brow0, bcol0,
                        g2 >> 3, (g2 & 7) * 64, tid);
        }
        asm volatile("cp.async.commit_group;" ::: "memory");

        uint32_t st = sb + (it % 3) * STAGEB;
#pragma unroll
        for (int ks = 0; ks < 4; ks++) {
            uint32_t ah[2][4], bh[2][4];
#pragma unroll
            for (int mt = 0; mt < 2; mt++)
                ldsm4(ah[mt], st + aoff[mt] + ks * 32);
#pragma unroll
            for (int p = 0; p < 2; p++)
                ldsm4(bh[p], st + TILEB + boff[p] + ks * 32);
#pragma unroll
            for (int mt = 0; mt < 2; mt++)
#pragma unroll
                for (int p = 0; p < 2; p++) {
                    mma16816(macc[mt][2 * p],     ah[mt], &bh[p][0]);
                    mma16816(macc[mt][2 * p + 1], ah[mt], &bh[p][2]);
                }
        }

        if ((it & 7) == 7) {
            int m = (gbase + it) >> 3;
#pragma unroll
            for (int mt = 0; mt < 2; mt++) {
                int ra = wm * 32 + mt * 16 + (lane >> 2);
                float sa = sim_sm[ra * 16 + m];
                float sb_ = sim_sm[(ra + 8) * 16 + m];
#pragma unroll
                for (int nt = 0; nt < 4; nt++) {
                    facc[mt][nt][0] += sa  * macc[mt][nt][0];
                    facc[mt][nt][1] += sa  * macc[mt][nt][1];
                    facc[mt][nt][2] += sb_ * macc[mt][nt][2];
                    facc[mt][nt][3] += sb_ * macc[mt][nt][3];
                    macc[mt][nt][0] = 0.f; macc[mt][nt][1] = 0.f;
                    macc[mt][nt][2] = 0.f; macc[mt][nt][3] = 0.f;
                }
            }
        }
    }

    if (split == 0) {
#pragma unroll
        for (int mt = 0; mt < 2; mt++) {
            int ra = wm * 32 + mt * 16 + (lane >> 2);
            for (int m = 0; m < 16; m++) {
                float sa = sim_sm[ra * 16 + m];
                float sb_ = sim_sm[(ra + 8) * 16 + m];
#pragma unroll
                for (int nt = 0; nt < 4; nt++) {
                    int col = wn * 32 + nt * 8 + 2 * (lane & 3);
                    float b0 = bias_sm[m * 128 + col];
                    float b1 = bias_sm[m * 128 + col + 1];
                    facc[mt][nt][0] += sa * b0;  facc[mt][nt][1] += sa * b1;
                    facc[mt][nt][2] += sb_ * b0; facc[mt][nt][3] += sb_ * b1;
                }
            }
        }
    }

#pragma unroll
    for (int mt = 0; mt < 2; mt++) {
        int ra = brow0 + wm * 32 + mt * 16 + (lane >> 2);
#pragma unroll
        for (int nt = 0; nt < 4; nt++) {
            int col = bcol0 + wn * 32 + nt * 8 + 2 * (lane & 3);
            atomicAdd(&out[(size_t)ra * U_SZ + col],       facc[mt][nt][0]);
            atomicAdd(&out[(size_t)ra * U_SZ + col + 1],   facc[mt][nt][1]);
            atomicAdd(&out[(size_t)(ra + 8) * U_SZ + col],     facc[mt][nt][2]);
            atomicAdd(&out[(size_t)(ra + 8) * U_SZ + col + 1], facc[mt][nt][3]);
        }
    }
}

// ---------------------------------------------------------------------------
extern "C" void kernel_launch(void* const* d_in, const int* in_sizes, int n_in,
                              void* d_out, int out_size)
{
    const float* x          = (const float*)d_in[0];
    const float* key_kernel = (const float*)d_in[1];
    const float* key_bias   = (const float*)d_in[2];
    const float* keys_map   = (const float*)d_in[3];
    const float* kernels    = (const float*)d_in[4];
    const float* biases     = (const float*)d_in[5];
    float* out = (float*)d_out;

    cudaFuncSetAttribute(pd_mma, cudaFuncAttributeMaxDynamicSharedMemorySize,
                         SMEM_TOTAL);
    cudaFuncSetAttribute(keyv_sim, cudaFuncAttributeMaxDynamicSharedMemorySize,
                         KV_SMEM);

    zero_out<<<(B_SZ * U_SZ) / (512 * 4), 512>>>((float4*)out);
    conv_x<<<(B_SZ * D_SZ) / (256 * 4), 256>>>(x);
    conv_w<<<dim3(16, 16, 16), dim3(32, 8)>>>(kernels);
    keyv_sim<<<B_SZ / 128, 256, KV_SMEM>>>(key_kernel, key_bias, keys_map);

    dim3 grid(U_SZ / 128, B_SZ / 128, 4);
    pd_mma<<<grid, 512, SMEM_TOTAL>>>(biases, out);
}

// round 13
// speedup vs baseline: 6.4330x; 1.0141x over previous
#include <cuda_runtime.h>
#include <cuda_fp16.h>
#include <cstdint>

#define B_SZ 8192
#define D_SZ 512
#define U_SZ 512
#define M_SZ 16

// ---------------------------------------------------------------------------
// Scratch (static __device__ — no allocations allowed)
// ---------------------------------------------------------------------------
__device__ float  g_sim[B_SZ * M_SZ];          // sim/16
__device__ __half g_xh[B_SZ * D_SZ];           // [b][d]
__device__ __half g_wh[M_SZ * U_SZ * D_SZ];    // [m][u][d]  (k-major B)
__device__ __half g_kkh[512 * 72];             // key_kernel fp16, padded [512][72]

// ---------------------------------------------------------------------------
// helpers
// ---------------------------------------------------------------------------
__device__ __forceinline__ uint32_t smem_u32(const void* p) {
    uint32_t a;
    asm("{ .reg .u64 t; cvta.to.shared.u64 t, %1; cvt.u32.u64 %0, t; }"
        : "=r"(a) : "l"(p));
    return a;
}
__device__ __forceinline__ void cp_async16(uint32_t saddr, const void* gaddr) {
    asm volatile("cp.async.cg.shared.global [%0], [%1], 16;"
                 :: "r"(saddr), "l"(gaddr) : "memory");
}
__device__ __forceinline__ void ldsm4(uint32_t* r, uint32_t a) {
    asm volatile("ldmatrix.sync.aligned.m8n8.x4.shared.b16 {%0,%1,%2,%3}, [%4];"
                 : "=r"(r[0]), "=r"(r[1]), "=r"(r[2]), "=r"(r[3]) : "r"(a));
}
__device__ __forceinline__ void ldsm4t(uint32_t* r, uint32_t a) {
    asm volatile("ldmatrix.sync.aligned.m8n8.x4.trans.shared.b16 {%0,%1,%2,%3}, [%4];"
                 : "=r"(r[0]), "=r"(r[1]), "=r"(r[2]), "=r"(r[3]) : "r"(a));
}
__device__ __forceinline__ void mma16816(float* c, const uint32_t* a, const uint32_t* b) {
    asm volatile(
        "mma.sync.aligned.m16n8k16.row.col.f32.f16.f16.f32 "
        "{%0,%1,%2,%3}, {%4,%5,%6,%7}, {%8,%9}, {%0,%1,%2,%3};"
        : "+f"(c[0]), "+f"(c[1]), "+f"(c[2]), "+f"(c[3])
        : "r"(a[0]), "r"(a[1]), "r"(a[2]), "r"(a[3]), "r"(b[0]), "r"(b[1]));
}

// ---------------------------------------------------------------------------
// prep_all — fused streaming prep, dispatch on blockIdx.x:
//   [0, 4096)      conv_w  (verified R6 body)
//   [4096, 5120)   conv_x  (fp32 -> fp16; 4 float4 PER THREAD — R12 bug fixed)
//   [5120, 6144)   zero-init of out (poisoned by harness)
//   [6144]         key_kernel fp32 -> fp16 padded image g_kkh[512][72]
// ---------------------------------------------------------------------------
__global__ __launch_bounds__(256) void prep_all(
    const float* __restrict__ x, const float* __restrict__ kern,
    const float* __restrict__ key_kernel, float4* __restrict__ out4)
{
    int b = blockIdx.x;
    int tid = threadIdx.x;

    if (b < 4096) {
        // ----- conv_w -----
        __shared__ float t[32][33];
        int m = b >> 8, u0 = ((b >> 4) & 15) * 32, d0 = (b & 15) * 32;
        int tx = tid & 31, ty = tid >> 5;
        const float* src = kern + (size_t)m * D_SZ * U_SZ;
#pragma unroll
        for (int j = 0; j < 4; j++)
            t[ty + 8 * j][tx] = src[(size_t)(d0 + ty + 8 * j) * U_SZ + u0 + tx];
        __syncthreads();
        size_t ob = (size_t)m * U_SZ * D_SZ;
#pragma unroll
        for (int j = 0; j < 4; j++) {
            float v = t[tx][ty + 8 * j];
            g_wh[ob + (size_t)(u0 + ty + 8 * j) * D_SZ + d0 + tx] =
                __float2half_rn(v);
        }
    } else if (b < 5120) {
        // ----- conv_x: 1024 blocks x 256 threads x 4 float4 = 4.19M floats ---
        uint32_t base = (uint32_t)(b - 4096) * 1024u + tid;   // float4 index
#pragma unroll
        for (int k = 0; k < 4; k++) {
            uint32_t i4 = base + k * 256u;
            float4 v = reinterpret_cast<const float4*>(x)[i4];
            __half2* ph = reinterpret_cast<__half2*>(g_xh) + (size_t)i4 * 2;
            ph[0] = __halves2half2(__float2half_rn(v.x), __float2half_rn(v.y));
            ph[1] = __halves2half2(__float2half_rn(v.z), __float2half_rn(v.w));
        }
    } else if (b < 6144) {
        // ----- zero out -----
        uint32_t base = (uint32_t)(b - 5120) * 1024u + tid;
#pragma unroll
        for (int k = 0; k < 4; k++)
            out4[base + k * 256u] = make_float4(0.f, 0.f, 0.f, 0.f);
    } else {
        // ----- key_kernel -> fp16 padded image -----
        const float4* kk4 = reinterpret_cast<const float4*>(key_kernel);
#pragma unroll
        for (int j = 0; j < 32; j++) {
            int i = tid + j * 256;              // 8192 float4
            int row = i >> 4, c4 = (i & 15) * 4;
            float4 v = kk4[i];
            __half2* dst = reinterpret_cast<__half2*>(g_kkh + row * 72 + c4);
            dst[0] = __halves2half2(__float2half_rn(v.x), __float2half_rn(v.y));
            dst[1] = __halves2half2(__float2half_rn(v.z), __float2half_rn(v.w));
        }
    }
}

// ---------------------------------------------------------------------------
// keyv_sim v2 — 128 blocks x 64 rows (full wave). kkh staged via linear
// cp.async copy of the precomputed padded image; warps 0-3 run the verified
// HMMA (A ldsm4, B ldsm4t natural-layout); all warps share dist epilogue.
// ---------------------------------------------------------------------------
#define KV_KKH 0                      // half [512][72] = 73728
#define KV_A   73728                  // 3 x (64*144) = 27648  (reused as kvs)
#define KV_KM  (73728 + 27648)        // f32 [16][65] = 4160
#define KV_BS  (KV_KM + 4160)         // f32 [64] = 256
#define KV_SMEM (KV_BS + 256)         // 105792

__global__ __launch_bounds__(256) void keyv_sim(
    const float* __restrict__ key_bias, const float* __restrict__ keys_map)
{
    extern __shared__ __align__(1024) char sm[];
    uint32_t sb = smem_u32(sm);
    int tid = threadIdx.x;
    int lane = tid & 31, w = tid >> 5;
    int b0 = blockIdx.x * 64;

    // stage keys_map (pad 65) + bias (plain LDG/STS; tiny)
    float* kmf = reinterpret_cast<float*>(sm + KV_KM);
    float* bs  = reinterpret_cast<float*>(sm + KV_BS);
    if (tid < 64) bs[tid] = key_bias[tid];
    kmf[(tid >> 4) * 65 + 4 * (tid & 15) + 0] = keys_map[(tid >> 4) * 64 + 4 * (tid & 15) + 0];
    kmf[(tid >> 4) * 65 + 4 * (tid & 15) + 1] = keys_map[(tid >> 4) * 64 + 4 * (tid & 15) + 1];
    kmf[(tid >> 4) * 65 + 4 * (tid & 15) + 2] = keys_map[(tid >> 4) * 64 + 4 * (tid & 15) + 2];
    kmf[(tid >> 4) * 65 + 4 * (tid & 15) + 3] = keys_map[(tid >> 4) * 64 + 4 * (tid & 15) + 3];

    // A chunk loader: 64 rows x 64 halves (8KB), 2 cp16/thread
    auto issue_A = [&](uint32_t st, int kc) {
#pragma unroll
        for (int j = 0; j < 2; j++) {
            int idx = tid + j * 256;
            int row = idx >> 3, seg = idx & 7;
            cp_async16(st + (uint32_t)(row * 144 + seg * 16),
                       g_xh + (size_t)(b0 + row) * D_SZ + kc * 64 + seg * 8);
        }
    };

    // group 0: kkh linear copy (4608 cp16) + A chunk 0
#pragma unroll
    for (int j = 0; j < 18; j++) {
        int idx = tid + j * 256;
        cp_async16(sb + KV_KKH + (uint32_t)idx * 16, g_kkh + (size_t)idx * 8);
    }
    issue_A(sb + KV_A, 0);
    asm volatile("cp.async.commit_group;" ::: "memory");
    issue_A(sb + KV_A + 9216, 1);
    asm volatile("cp.async.commit_group;" ::: "memory");

    float acc[8][4];
#pragma unroll
    for (int j = 0; j < 8; j++)
#pragma unroll
        for (int i = 0; i < 4; i++) acc[j][i] = 0.f;

    int q = lane >> 3, rr = lane & 7;
    uint32_t aoffb = (uint32_t)((w * 16 + (lane & 15)) * 144 + (lane >> 4) * 16);
    uint32_t boffb = (uint32_t)(KV_KKH + ((q & 1) * 8 + rr) * 144 + ((q >> 1) * 8) * 2);

    for (int kc = 0; kc < 8; kc++) {
        asm volatile("cp.async.wait_group 1;" ::: "memory");
        __syncthreads();       // group kc (and kkh at kc=0) visible to all
        int k2 = kc + 2;
        if (k2 < 8) issue_A(sb + KV_A + (k2 % 3) * 9216, k2);
        asm volatile("cp.async.commit_group;" ::: "memory");

        if (w < 4) {
            uint32_t ab = sb + KV_A + (kc % 3) * 9216;
#pragma unroll
            for (int ks = 0; ks < 4; ks++) {
                uint32_t ah[4], bf[4][4];
                ldsm4(ah, ab + aoffb + ks * 32);
                uint32_t kb = sb + boffb + (uint32_t)((kc * 64 + ks * 16) * 144);
#pragma unroll
                for (int p = 0; p < 4; p++)
                    ldsm4t(bf[p], kb + p * 32);
#pragma unroll
                for (int p = 0; p < 4; p++) {
                    mma16816(acc[2 * p],     ah, &bf[p][0]);
                    mma16816(acc[2 * p + 1], ah, &bf[p][2]);
                }
            }
        }
    }

    // keyv (+bias) to smem (reuse A region), then distances
    __syncthreads();                      // all ldsm reads of A buffers done
    float* kvs = reinterpret_cast<float*>(sm + KV_A);    // [64][68]
    if (w < 4) {
        int r0 = w * 16 + (lane >> 2);
        int c0 = 2 * (lane & 3);
#pragma unroll
        for (int j = 0; j < 8; j++) {
            int col = j * 8 + c0;
            kvs[r0 * 68 + col]           = acc[j][0] + bs[col];
            kvs[r0 * 68 + col + 1]       = acc[j][1] + bs[col + 1];
            kvs[(r0 + 8) * 68 + col]     = acc[j][2] + bs[col];
            kvs[(r0 + 8) * 68 + col + 1] = acc[j][3] + bs[col + 1];
        }
    }
    __syncthreads();

#pragma unroll
    for (int i = 0; i < 4; i++) {
        int task = tid + i * 256;          // 1024 = 64 rows x 16 modes
        int row = task >> 4, mode = task & 15;
        float d2 = 0.f;
#pragma unroll 8
        for (int kk = 0; kk < 64; kk++) {
            float diff = kvs[row * 68 + kk] - kmf[mode * 65 + kk];
            d2 += diff * diff;
        }
        g_sim[(size_t)(b0 + row) * M_SZ + mode] =
            1.0f / (16.0f * (sqrtf(d2) + 1.0f));
    }
}

// ---------------------------------------------------------------------------
// Main HMMA GEMM — R8's verified 128x128/BK=64 mainloop, SPLIT-K x4 (R10).
// UNCHANGED from R11.
// ---------------------------------------------------------------------------
#define ROWB 144
#define TILEB (128 * ROWB)          // 18432
#define STAGEB (2 * TILEB)          // 36864
#define SM_BIAS (3 * STAGEB)        // 110592
#define SM_SIM  (SM_BIAS + 16 * 128 * 4)
#define SMEM_TOTAL (SM_SIM + 128 * 16 * 4)   // 126976

__device__ __forceinline__ void issue_loads(
    uint32_t st, int brow0, int bcol0, int m, int d0, int tid)
{
#pragma unroll
    for (int j = 0; j < 4; j++) {
        int idx = tid + j * 512;
        int tile = idx >> 10;
        int row = (idx >> 3) & 127;
        int seg = idx & 7;
        uint32_t dst = st + tile * TILEB + (uint32_t)(row * ROWB + seg * 16);
        const __half* g = (tile == 0)
            ? g_xh + (size_t)(brow0 + row) * D_SZ + d0 + seg * 8
            : g_wh + ((size_t)m * U_SZ + bcol0 + row) * D_SZ + d0 + seg * 8;
        cp_async16(dst, g);
    }
}

__global__ __launch_bounds__(512, 1) void pd_mma(
    const float* __restrict__ biases, float* __restrict__ out)
{
    extern __shared__ __align__(1024) char smem[];
    uint32_t sb = smem_u32(smem);
    int tid = threadIdx.x;
    int lane = tid & 31, warp = tid >> 5;
    int wm = warp & 3, wn = warp >> 2;
    int brow0 = blockIdx.y * 128;
    int bcol0 = blockIdx.x * 128;
    int split = blockIdx.z;
    int gbase = split * 32;

    float* bias_sm = reinterpret_cast<float*>(smem + SM_BIAS);
    float* sim_sm  = reinterpret_cast<float*>(smem + SM_SIM);
    for (int i = tid; i < 16 * 128; i += 512)
        bias_sm[i] = biases[(i >> 7) * U_SZ + bcol0 + (i & 127)];
    for (int i = tid; i < 128 * 16; i += 512)
        sim_sm[i] = g_sim[(brow0 + (i >> 4)) * M_SZ + (i & 15)];

    uint32_t aoff[2], boff[2];
#pragma unroll
    for (int mt = 0; mt < 2; mt++)
        aoff[mt] = (uint32_t)((wm * 32 + mt * 16 + (lane & 15)) * ROWB +
                              ((lane >> 4) * 16));
#pragma unroll
    for (int p = 0; p < 2; p++)
        boff[p] = (uint32_t)((wn * 32 + p * 16 + ((lane >> 4) * 8) + (lane & 7)) * ROWB +
                             (((lane >> 3) & 1) * 16));

    float macc[2][4][4], facc[2][4][4];
#pragma unroll
    for (int mt = 0; mt < 2; mt++)
#pragma unroll
        for (int nt = 0; nt < 4; nt++)
#pragma unroll
            for (int i = 0; i < 4; i++) { macc[mt][nt][i] = 0.f; facc[mt][nt][i] = 0.f; }

    issue_loads(sb, brow0, bcol0, gbase >> 3, (gbase & 7) * 64, tid);
    asm volatile("cp.async.commit_group;" ::: "memory");
    issue_loads(sb + STAGEB, brow0, bcol0, (gbase + 1) >> 3, ((gbase + 1) & 7) * 64, tid);
    asm volatile("cp.async.commit_group;" ::: "memory");

    for (int it = 0; it < 32; it++) {
        asm volatile("cp.async.wait_group 1;" ::: "memory");
        __syncthreads();
        int it2 = it + 2;
        if (it2 < 32) {
            int g2 = gbase + it2;
            issue_loads(sb + (it2 % 3) * STAGEB, brow0, bcol0,
                        g2 >> 3, (g2 & 7) * 64, tid);
        }
        asm volatile("cp.async.commit_group;" ::: "memory");

        uint32_t st = sb + (it % 3) * STAGEB;
#pragma unroll
        for (int ks = 0; ks < 4; ks++) {
            uint32_t ah[2][4], bh[2][4];
#pragma unroll
            for (int mt = 0; mt < 2; mt++)
                ldsm4(ah[mt], st + aoff[mt] + ks * 32);
#pragma unroll
            for (int p = 0; p < 2; p++)
                ldsm4(bh[p], st + TILEB + boff[p] + ks * 32);
#pragma unroll
            for (int mt = 0; mt < 2; mt++)
#pragma unroll
                for (int p = 0; p < 2; p++) {
                    mma16816(macc[mt][2 * p],     ah[mt], &bh[p][0]);
                    mma16816(macc[mt][2 * p + 1], ah[mt], &bh[p][2]);
                }
        }

        if ((it & 7) == 7) {
            int m = (gbase + it) >> 3;
#pragma unroll
            for (int mt = 0; mt < 2; mt++) {
                int ra = wm * 32 + mt * 16 + (lane >> 2);
                float sa = sim_sm[ra * 16 + m];
                float sb_ = sim_sm[(ra + 8) * 16 + m];
#pragma unroll
                for (int nt = 0; nt < 4; nt++) {
                    facc[mt][nt][0] += sa  * macc[mt][nt][0];
                    facc[mt][nt][1] += sa  * macc[mt][nt][1];
                    facc[mt][nt][2] += sb_ * macc[mt][nt][2];
                    facc[mt][nt][3] += sb_ * macc[mt][nt][3];
                    macc[mt][nt][0] = 0.f; macc[mt][nt][1] = 0.f;
                    macc[mt][nt][2] = 0.f; macc[mt][nt][3] = 0.f;
                }
            }
        }
    }

    if (split == 0) {
#pragma unroll
        for (int mt = 0; mt < 2; mt++) {
            int ra = wm * 32 + mt * 16 + (lane >> 2);
            for (int m = 0; m < 16; m++) {
                float sa = sim_sm[ra * 16 + m];
                float sb_ = sim_sm[(ra + 8) * 16 + m];
#pragma unroll
                for (int nt = 0; nt < 4; nt++) {
                    int col = wn * 32 + nt * 8 + 2 * (lane & 3);
                    float b0 = bias_sm[m * 128 + col];
                    float b1 = bias_sm[m * 128 + col + 1];
                    facc[mt][nt][0] += sa * b0;  facc[mt][nt][1] += sa * b1;
                    facc[mt][nt][2] += sb_ * b0; facc[mt][nt][3] += sb_ * b1;
                }
            }
        }
    }

#pragma unroll
    for (int mt = 0; mt < 2; mt++) {
        int ra = brow0 + wm * 32 + mt * 16 + (lane >> 2);
#pragma unroll
        for (int nt = 0; nt < 4; nt++) {
            int col = bcol0 + wn * 32 + nt * 8 + 2 * (lane & 3);
            atomicAdd(&out[(size_t)ra * U_SZ + col],       facc[mt][nt][0]);
            atomicAdd(&out[(size_t)ra * U_SZ + col + 1],   facc[mt][nt][1]);
            atomicAdd(&out[(size_t)(ra + 8) * U_SZ + col],     facc[mt][nt][2]);
            atomicAdd(&out[(size_t)(ra + 8) * U_SZ + col + 1], facc[mt][nt][3]);
        }
    }
}

// ---------------------------------------------------------------------------
extern "C" void kernel_launch(void* const* d_in, const int* in_sizes, int n_in,
                              void* d_out, int out_size)
{
    const float* x          = (const float*)d_in[0];
    const float* key_kernel = (const float*)d_in[1];
    const float* key_bias   = (const float*)d_in[2];
    const float* keys_map   = (const float*)d_in[3];
    const float* kernels    = (const float*)d_in[4];
    const float* biases     = (const float*)d_in[5];
    float* out = (float*)d_out;

    cudaFuncSetAttribute(pd_mma, cudaFuncAttributeMaxDynamicSharedMemorySize,
                         SMEM_TOTAL);
    cudaFuncSetAttribute(keyv_sim, cudaFuncAttributeMaxDynamicSharedMemorySize,
                         KV_SMEM);

    prep_all<<<6145, 256>>>(x, kernels, key_kernel, (float4*)out);
    keyv_sim<<<B_SZ / 64, 256, KV_SMEM>>>(key_bias, keys_map);

    dim3 grid(U_SZ / 128, B_SZ / 128, 4);
    pd_mma<<<grid, 512, SMEM_TOTAL>>>(biases, out);
}

// round 14
// speedup vs baseline: 7.1258x; 1.1077x over previous
#include <cuda_runtime.h>
#include <cuda_fp16.h>
#include <cstdint>

#define B_SZ 8192
#define D_SZ 512
#define U_SZ 512
#define M_SZ 16

// ---------------------------------------------------------------------------
// Scratch (static __device__ — no allocations allowed)
// ---------------------------------------------------------------------------
__device__ float  g_sim[B_SZ * M_SZ];          // sim/16
__device__ __half g_xh[B_SZ * D_SZ];           // [b][d]
__device__ __half g_wh[M_SZ * U_SZ * D_SZ];    // [m][u][d]  (k-major B)
__device__ __half g_kkh[512 * 72];             // key_kernel fp16, padded [512][72]

// ---------------------------------------------------------------------------
// helpers
// ---------------------------------------------------------------------------
__device__ __forceinline__ uint32_t smem_u32(const void* p) {
    uint32_t a;
    asm("{ .reg .u64 t; cvta.to.shared.u64 t, %1; cvt.u32.u64 %0, t; }"
        : "=r"(a) : "l"(p));
    return a;
}
__device__ __forceinline__ void cp_async16(uint32_t saddr, const void* gaddr) {
    asm volatile("cp.async.cg.shared.global [%0], [%1], 16;"
                 :: "r"(saddr), "l"(gaddr) : "memory");
}
__device__ __forceinline__ void ldsm4(uint32_t* r, uint32_t a) {
    asm volatile("ldmatrix.sync.aligned.m8n8.x4.shared.b16 {%0,%1,%2,%3}, [%4];"
                 : "=r"(r[0]), "=r"(r[1]), "=r"(r[2]), "=r"(r[3]) : "r"(a));
}
__device__ __forceinline__ void ldsm4t(uint32_t* r, uint32_t a) {
    asm volatile("ldmatrix.sync.aligned.m8n8.x4.trans.shared.b16 {%0,%1,%2,%3}, [%4];"
                 : "=r"(r[0]), "=r"(r[1]), "=r"(r[2]), "=r"(r[3]) : "r"(a));
}
__device__ __forceinline__ void mma16816(float* c, const uint32_t* a, const uint32_t* b) {
    asm volatile(
        "mma.sync.aligned.m16n8k16.row.col.f32.f16.f16.f32 "
        "{%0,%1,%2,%3}, {%4,%5,%6,%7}, {%8,%9}, {%0,%1,%2,%3};"
        : "+f"(c[0]), "+f"(c[1]), "+f"(c[2]), "+f"(c[3])
        : "r"(a[0]), "r"(a[1]), "r"(a[2]), "r"(a[3]), "r"(b[0]), "r"(b[1]));
}

// ---------------------------------------------------------------------------
// prep_all — fused streaming prep (verified R13, at DRAM floor). UNCHANGED.
// ---------------------------------------------------------------------------
__global__ __launch_bounds__(256) void prep_all(
    const float* __restrict__ x, const float* __restrict__ kern,
    const float* __restrict__ key_kernel, float4* __restrict__ out4)
{
    int b = blockIdx.x;
    int tid = threadIdx.x;

    if (b < 4096) {
        __shared__ float t[32][33];
        int m = b >> 8, u0 = ((b >> 4) & 15) * 32, d0 = (b & 15) * 32;
        int tx = tid & 31, ty = tid >> 5;
        const float* src = kern + (size_t)m * D_SZ * U_SZ;
#pragma unroll
        for (int j = 0; j < 4; j++)
            t[ty + 8 * j][tx] = src[(size_t)(d0 + ty + 8 * j) * U_SZ + u0 + tx];
        __syncthreads();
        size_t ob = (size_t)m * U_SZ * D_SZ;
#pragma unroll
        for (int j = 0; j < 4; j++) {
            float v = t[tx][ty + 8 * j];
            g_wh[ob + (size_t)(u0 + ty + 8 * j) * D_SZ + d0 + tx] =
                __float2half_rn(v);
        }
    } else if (b < 5120) {
        uint32_t base = (uint32_t)(b - 4096) * 1024u + tid;
#pragma unroll
        for (int k = 0; k < 4; k++) {
            uint32_t i4 = base + k * 256u;
            float4 v = reinterpret_cast<const float4*>(x)[i4];
            __half2* ph = reinterpret_cast<__half2*>(g_xh) + (size_t)i4 * 2;
            ph[0] = __halves2half2(__float2half_rn(v.x), __float2half_rn(v.y));
            ph[1] = __halves2half2(__float2half_rn(v.z), __float2half_rn(v.w));
        }
    } else if (b < 6144) {
        uint32_t base = (uint32_t)(b - 5120) * 1024u + tid;
#pragma unroll
        for (int k = 0; k < 4; k++)
            out4[base + k * 256u] = make_float4(0.f, 0.f, 0.f, 0.f);
    } else {
        const float4* kk4 = reinterpret_cast<const float4*>(key_kernel);
#pragma unroll
        for (int j = 0; j < 32; j++) {
            int i = tid + j * 256;
            int row = i >> 4, c4 = (i & 15) * 4;
            float4 v = kk4[i];
            __half2* dst = reinterpret_cast<__half2*>(g_kkh + row * 72 + c4);
            dst[0] = __halves2half2(__float2half_rn(v.x), __float2half_rn(v.y));
            dst[1] = __halves2half2(__float2half_rn(v.z), __float2half_rn(v.w));
        }
    }
}

// ---------------------------------------------------------------------------
// keyv_sim v2 (verified R13). UNCHANGED.
// ---------------------------------------------------------------------------
#define KV_KKH 0                      // half [512][72] = 73728
#define KV_A   73728                  // 3 x (64*144) = 27648  (reused as kvs)
#define KV_KM  (73728 + 27648)        // f32 [16][65] = 4160
#define KV_BS  (KV_KM + 4160)         // f32 [64] = 256
#define KV_SMEM (KV_BS + 256)         // 105792

__global__ __launch_bounds__(256) void keyv_sim(
    const float* __restrict__ key_bias, const float* __restrict__ keys_map)
{
    extern __shared__ __align__(1024) char sm[];
    uint32_t sb = smem_u32(sm);
    int tid = threadIdx.x;
    int lane = tid & 31, w = tid >> 5;
    int b0 = blockIdx.x * 64;

    float* kmf = reinterpret_cast<float*>(sm + KV_KM);
    float* bs  = reinterpret_cast<float*>(sm + KV_BS);
    if (tid < 64) bs[tid] = key_bias[tid];
    kmf[(tid >> 4) * 65 + 4 * (tid & 15) + 0] = keys_map[(tid >> 4) * 64 + 4 * (tid & 15) + 0];
    kmf[(tid >> 4) * 65 + 4 * (tid & 15) + 1] = keys_map[(tid >> 4) * 64 + 4 * (tid & 15) + 1];
    kmf[(tid >> 4) * 65 + 4 * (tid & 15) + 2] = keys_map[(tid >> 4) * 64 + 4 * (tid & 15) + 2];
    kmf[(tid >> 4) * 65 + 4 * (tid & 15) + 3] = keys_map[(tid >> 4) * 64 + 4 * (tid & 15) + 3];

    auto issue_A = [&](uint32_t st, int kc) {
#pragma unroll
        for (int j = 0; j < 2; j++) {
            int idx = tid + j * 256;
            int row = idx >> 3, seg = idx & 7;
            cp_async16(st + (uint32_t)(row * 144 + seg * 16),
                       g_xh + (size_t)(b0 + row) * D_SZ + kc * 64 + seg * 8);
        }
    };

#pragma unroll
    for (int j = 0; j < 18; j++) {
        int idx = tid + j * 256;
        cp_async16(sb + KV_KKH + (uint32_t)idx * 16, g_kkh + (size_t)idx * 8);
    }
    issue_A(sb + KV_A, 0);
    asm volatile("cp.async.commit_group;" ::: "memory");
    issue_A(sb + KV_A + 9216, 1);
    asm volatile("cp.async.commit_group;" ::: "memory");

    float acc[8][4];
#pragma unroll
    for (int j = 0; j < 8; j++)
#pragma unroll
        for (int i = 0; i < 4; i++) acc[j][i] = 0.f;

    int q = lane >> 3, rr = lane & 7;
    uint32_t aoffb = (uint32_t)((w * 16 + (lane & 15)) * 144 + (lane >> 4) * 16);
    uint32_t boffb = (uint32_t)(KV_KKH + ((q & 1) * 8 + rr) * 144 + ((q >> 1) * 8) * 2);

    for (int kc = 0; kc < 8; kc++) {
        asm volatile("cp.async.wait_group 1;" ::: "memory");
        __syncthreads();
        int k2 = kc + 2;
        if (k2 < 8) issue_A(sb + KV_A + (k2 % 3) * 9216, k2);
        asm volatile("cp.async.commit_group;" ::: "memory");

        if (w < 4) {
            uint32_t ab = sb + KV_A + (kc % 3) * 9216;
#pragma unroll
            for (int ks = 0; ks < 4; ks++) {
                uint32_t ah[4], bf[4][4];
                ldsm4(ah, ab + aoffb + ks * 32);
                uint32_t kb = sb + boffb + (uint32_t)((kc * 64 + ks * 16) * 144);
#pragma unroll
                for (int p = 0; p < 4; p++)
                    ldsm4t(bf[p], kb + p * 32);
#pragma unroll
                for (int p = 0; p < 4; p++) {
                    mma16816(acc[2 * p],     ah, &bf[p][0]);
                    mma16816(acc[2 * p + 1], ah, &bf[p][2]);
                }
            }
        }
    }

    __syncthreads();
    float* kvs = reinterpret_cast<float*>(sm + KV_A);    // [64][68]
    if (w < 4) {
        int r0 = w * 16 + (lane >> 2);
        int c0 = 2 * (lane & 3);
#pragma unroll
        for (int j = 0; j < 8; j++) {
            int col = j * 8 + c0;
            kvs[r0 * 68 + col]           = acc[j][0] + bs[col];
            kvs[r0 * 68 + col + 1]       = acc[j][1] + bs[col + 1];
            kvs[(r0 + 8) * 68 + col]     = acc[j][2] + bs[col];
            kvs[(r0 + 8) * 68 + col + 1] = acc[j][3] + bs[col + 1];
        }
    }
    __syncthreads();

#pragma unroll
    for (int i = 0; i < 4; i++) {
        int task = tid + i * 256;
        int row = task >> 4, mode = task & 15;
        float d2 = 0.f;
#pragma unroll 8
        for (int kk = 0; kk < 64; kk++) {
            float diff = kvs[row * 68 + kk] - kmf[mode * 65 + kk];
            d2 += diff * diff;
        }
        g_sim[(size_t)(b0 + row) * M_SZ + mode] =
            1.0f / (16.0f * (sqrtf(d2) + 1.0f));
    }
}

// ---------------------------------------------------------------------------
// Main HMMA GEMM — R10 split-K x4, now BK=128 / 2-stage (16 iters/CTA).
// Same hazard ordering as verified loop: wait_group -> syncthreads -> issue.
// Fold every 4 iterations (one mode = 512 k = 4 x BK128).
// ---------------------------------------------------------------------------
#define ROWB 272         // 128 fp16 cols + 16B pad
#define TILEB (128 * ROWB)          // 34816
#define STAGEB (2 * TILEB)          // 69632
#define SM_BIAS (2 * STAGEB)        // 139264
#define SM_SIM  (SM_BIAS + 16 * 128 * 4)
#define SMEM_TOTAL (SM_SIM + 128 * 16 * 4)   // 155648

__device__ __forceinline__ void issue_loads(
    uint32_t st, int brow0, int bcol0, int g, int tid)
{
    int m = g >> 2;
    int d0 = (g & 3) * 128;
#pragma unroll
    for (int j = 0; j < 8; j++) {
        int idx = tid + j * 512;            // 4096 chunks of 16B
        int tile = idx >> 11;
        int row = (idx >> 4) & 127;
        int seg = idx & 15;
        uint32_t dst = st + tile * TILEB + (uint32_t)(row * ROWB + seg * 16);
        const __half* gp = (tile == 0)
            ? g_xh + (size_t)(brow0 + row) * D_SZ + d0 + seg * 8
            : g_wh + ((size_t)m * U_SZ + bcol0 + row) * D_SZ + d0 + seg * 8;
        cp_async16(dst, gp);
    }
}

__global__ __launch_bounds__(512, 1) void pd_mma(
    const float* __restrict__ biases, float* __restrict__ out)
{
    extern __shared__ __align__(1024) char smem[];
    uint32_t sb = smem_u32(smem);
    int tid = threadIdx.x;
    int lane = tid & 31, warp = tid >> 5;
    int wm = warp & 3, wn = warp >> 2;
    int brow0 = blockIdx.y * 128;
    int bcol0 = blockIdx.x * 128;
    int split = blockIdx.z;
    int gbase = split * 16;                // BK128 iteration base

    float* bias_sm = reinterpret_cast<float*>(smem + SM_BIAS);
    float* sim_sm  = reinterpret_cast<float*>(smem + SM_SIM);
    for (int i = tid; i < 16 * 128; i += 512)
        bias_sm[i] = biases[(i >> 7) * U_SZ + bcol0 + (i & 127)];
    for (int i = tid; i < 128 * 16; i += 512)
        sim_sm[i] = g_sim[(brow0 + (i >> 4)) * M_SZ + (i & 15)];

    uint32_t aoff[2], boff[2];
#pragma unroll
    for (int mt = 0; mt < 2; mt++)
        aoff[mt] = (uint32_t)((wm * 32 + mt * 16 + (lane & 15)) * ROWB +
                              ((lane >> 4) * 16));
#pragma unroll
    for (int p = 0; p < 2; p++)
        boff[p] = (uint32_t)((wn * 32 + p * 16 + ((lane >> 4) * 8) + (lane & 7)) * ROWB +
                             (((lane >> 3) & 1) * 16));

    float macc[2][4][4], facc[2][4][4];
#pragma unroll
    for (int mt = 0; mt < 2; mt++)
#pragma unroll
        for (int nt = 0; nt < 4; nt++)
#pragma unroll
            for (int i = 0; i < 4; i++) { macc[mt][nt][i] = 0.f; facc[mt][nt][i] = 0.f; }

    // prologue: stage 0 only (2-stage, distance-1)
    issue_loads(sb, brow0, bcol0, gbase, tid);
    asm volatile("cp.async.commit_group;" ::: "memory");

    for (int it = 0; it < 16; it++) {
        // only group `it` is outstanding here
        asm volatile("cp.async.wait_group 0;" ::: "memory");
        // group `it` visible to all threads; all warps done reading buffer
        // (it-1)&1 — safe to overwrite with group it+1
        __syncthreads();
        if (it + 1 < 16) {
            issue_loads(sb + ((it + 1) & 1) * STAGEB, brow0, bcol0,
                        gbase + it + 1, tid);
            asm volatile("cp.async.commit_group;" ::: "memory");
        }

        uint32_t st = sb + (it & 1) * STAGEB;
#pragma unroll
        for (int ks = 0; ks < 8; ks++) {
            uint32_t ah[2][4], bh[2][4];
#pragma unroll
            for (int mt = 0; mt < 2; mt++)
                ldsm4(ah[mt], st + aoff[mt] + ks * 32);
#pragma unroll
            for (int p = 0; p < 2; p++)
                ldsm4(bh[p], st + TILEB + boff[p] + ks * 32);
#pragma unroll
            for (int mt = 0; mt < 2; mt++)
#pragma unroll
                for (int p = 0; p < 2; p++) {
                    mma16816(macc[mt][2 * p],     ah[mt], &bh[p][0]);
                    mma16816(macc[mt][2 * p + 1], ah[mt], &bh[p][2]);
                }
        }

        if ((it & 3) == 3) {          // mode boundary: fold partials
            int m = (gbase + it) >> 2;
#pragma unroll
            for (int mt = 0; mt < 2; mt++) {
                int ra = wm * 32 + mt * 16 + (lane >> 2);
                float sa = sim_sm[ra * 16 + m];
                float sb_ = sim_sm[(ra + 8) * 16 + m];
#pragma unroll
                for (int nt = 0; nt < 4; nt++) {
                    facc[mt][nt][0] += sa  * macc[mt][nt][0];
                    facc[mt][nt][1] += sa  * macc[mt][nt][1];
                    facc[mt][nt][2] += sb_ * macc[mt][nt][2];
                    facc[mt][nt][3] += sb_ * macc[mt][nt][3];
                    macc[mt][nt][0] = 0.f; macc[mt][nt][1] = 0.f;
                    macc[mt][nt][2] = 0.f; macc[mt][nt][3] = 0.f;
                }
            }
        }
    }

    if (split == 0) {
#pragma unroll
        for (int mt = 0; mt < 2; mt++) {
            int ra = wm * 32 + mt * 16 + (lane >> 2);
            for (int m = 0; m < 16; m++) {
                float sa = sim_sm[ra * 16 + m];
                float sb_ = sim_sm[(ra + 8) * 16 + m];
#pragma unroll
                for (int nt = 0; nt < 4; nt++) {
                    int col = wn * 32 + nt * 8 + 2 * (lane & 3);
                    float b0 = bias_sm[m * 128 + col];
                    float b1 = bias_sm[m * 128 + col + 1];
                    facc[mt][nt][0] += sa * b0;  facc[mt][nt][1] += sa * b1;
                    facc[mt][nt][2] += sb_ * b0; facc[mt][nt][3] += sb_ * b1;
                }
            }
        }
    }

#pragma unroll
    for (int mt = 0; mt < 2; mt++) {
        int ra = brow0 + wm * 32 + mt * 16 + (lane >> 2);
#pragma unroll
        for (int nt = 0; nt < 4; nt++) {
            int col = bcol0 + wn * 32 + nt * 8 + 2 * (lane & 3);
            atomicAdd(&out[(size_t)ra * U_SZ + col],       facc[mt][nt][0]);
            atomicAdd(&out[(size_t)ra * U_SZ + col + 1],   facc[mt][nt][1]);
            atomicAdd(&out[(size_t)(ra + 8) * U_SZ + col],     facc[mt][nt][2]);
            atomicAdd(&out[(size_t)(ra + 8) * U_SZ + col + 1], facc[mt][nt][3]);
        }
    }
}

// ---------------------------------------------------------------------------
extern "C" void kernel_launch(void* const* d_in, const int* in_sizes, int n_in,
                              void* d_out, int out_size)
{
    const float* x          = (const float*)d_in[0];
    const float* key_kernel = (const float*)d_in[1];
    const float* key_bias   = (const float*)d_in[2];
    const float* keys_map   = (const float*)d_in[3];
    const float* kernels    = (const float*)d_in[4];
    const float* biases     = (const float*)d_in[5];
    float* out = (float*)d_out;

    cudaFuncSetAttribute(pd_mma, cudaFuncAttributeMaxDynamicSharedMemorySize,
                         SMEM_TOTAL);
    cudaFuncSetAttribute(keyv_sim, cudaFuncAttributeMaxDynamicSharedMemorySize,
                         KV_SMEM);

    prep_all<<<6145, 256>>>(x, kernels, key_kernel, (float4*)out);
    keyv_sim<<<B_SZ / 64, 256, KV_SMEM>>>(key_bias, keys_map);

    dim3 grid(U_SZ / 128, B_SZ / 128, 4);
    pd_mma<<<grid, 512, SMEM_TOTAL>>>(biases, out);
}